// round 7
// baseline (speedup 1.0000x reference)
#include <cuda_runtime.h>
#include <cuda_fp16.h>
#include <cstdint>
#include <cstddef>

#define EPSV 1e-5f

// problem dims (fixed)
#define NB 2
#define NC 64
#define NT 2048
#define NF 64
#define NH 4
#define NHC 4
#define NVC 16
#define DQK 256   // NHC*NF
#define DV  1024  // NVC*NF
#define NHB 8     // NH*NB

// ---------------- scratch (device globals; no allocations allowed) ----------
__device__ float  g_Q[(size_t)NHB * NT * DQK];   // 16 MB
__device__ float  g_K[(size_t)NHB * NT * DQK];   // 16 MB
__device__ __half g_V[(size_t)NHB * NT * DV];    // 32 MB
__device__ __half g_Vt[(size_t)NHB * DV * NT];   // 32 MB  V^T per z: [dv][t]
__device__ __half g_E[(size_t)NHB * NT * NT];    // 64 MB  exp(alpha*S)
__device__ float  g_O[(size_t)NHB * NT * DV];    // 64 MB

// ---------------- helpers ----------------------------------------------------
__device__ __forceinline__ uint32_t smem_u32(const void* p) {
    uint32_t a;
    asm("{ .reg .u64 t; cvta.to.shared.u64 t, %1; cvt.u32.u64 %0, t; }" : "=r"(a) : "l"(p));
    return a;
}
__device__ __forceinline__ float to_tf32(float x) {
    asm("cvt.rna.tf32.f32 %0, %1;" : "=f"(x) : "f"(x));
    return x;
}
__device__ __forceinline__ void cp_async16(uint32_t dst, const void* src) {
    asm volatile("cp.async.cg.shared.global [%0], [%1], 16;" :: "r"(dst), "l"(src) : "memory");
}
__device__ __forceinline__ void cp_commit() { asm volatile("cp.async.commit_group;" ::: "memory"); }
template <int N> __device__ __forceinline__ void cp_wait() {
    asm volatile("cp.async.wait_group %0;" :: "n"(N) : "memory");
}
__device__ __forceinline__ void mma_tf32(float* c, const uint32_t* a, const uint32_t* b) {
    asm volatile(
        "mma.sync.aligned.m16n8k8.row.col.f32.tf32.tf32.f32 "
        "{%0,%1,%2,%3}, {%4,%5,%6,%7}, {%8,%9}, {%0,%1,%2,%3};"
        : "+f"(c[0]), "+f"(c[1]), "+f"(c[2]), "+f"(c[3])
        : "r"(a[0]), "r"(a[1]), "r"(a[2]), "r"(a[3]), "r"(b[0]), "r"(b[1]));
}
__device__ __forceinline__ void mma_f16(float* c, const uint32_t* a, const uint32_t* b) {
    asm volatile(
        "mma.sync.aligned.m16n8k16.row.col.f32.f16.f16.f32 "
        "{%0,%1,%2,%3}, {%4,%5,%6,%7}, {%8,%9}, {%0,%1,%2,%3};"
        : "+f"(c[0]), "+f"(c[1]), "+f"(c[2]), "+f"(c[3])
        : "r"(a[0]), "r"(a[1]), "r"(a[2]), "r"(a[3]), "r"(b[0]), "r"(b[1]));
}
__device__ __forceinline__ float2 h2f2(uint32_t u) {
    return __half22float2(*reinterpret_cast<__half2*>(&u));
}

// ================= GEMM 1 (tf32): E = fp16(exp(alpha * Q K^T)) ===============
#define BM 128
#define BN 256
#define BK 32
#define A_STRIDE 36
#define B_STRIDE 36
#define A_TILE_FLOATS (BM * A_STRIDE)
#define B1_TILE_FLOATS (BN * B_STRIDE)
#define STAGE1_BYTES ((A_TILE_FLOATS + B1_TILE_FLOATS) * 4) // 55296
#define NSTG 3
#define SMEM_G1 (NSTG * STAGE1_BYTES)

__global__ __launch_bounds__(256, 1) void gemm_qk_exp(
    const float* __restrict__ A, const float* __restrict__ B, __half* __restrict__ C,
    float alpha, size_t sA, size_t sB, size_t sC)
{
    extern __shared__ char smem[];
    const int tid = threadIdx.x;
    const int wid = tid >> 5;
    const int lane = tid & 31;
    const int g = lane >> 2;
    const int tc = lane & 3;
    const int K = DQK;

    A += (size_t)blockIdx.z * sA;
    B += (size_t)blockIdx.z * sB;
    C += (size_t)blockIdx.z * sC;
    const int bm = blockIdx.y * BM;
    const int bn = blockIdx.x * BN;
    const int wm = (wid & 1) * 64;
    const int wn = (wid >> 1) * 64;

    float acc[4][8][4];
#pragma unroll
    for (int mt = 0; mt < 4; mt++)
#pragma unroll
        for (int nt = 0; nt < 8; nt++)
#pragma unroll
            for (int i = 0; i < 4; i++) acc[mt][nt][i] = 0.f;

    const int nk = K / BK;

#define ISSUE1(it) do {                                                        \
        int _st = (it) % NSTG;                                                 \
        uint32_t _as = smem_u32(smem) + _st * STAGE1_BYTES;                    \
        uint32_t _bs = _as + A_TILE_FLOATS * 4;                                \
        const float* _ga = A + (size_t)bm * K + (size_t)(it) * BK;             \
        const float* _gb = B + (size_t)bn * K + (size_t)(it) * BK;             \
        _Pragma("unroll")                                                      \
        for (int j = 0; j < 4; j++) {                                          \
            int idx = tid + j * 256;                                           \
            int row = idx >> 3, c = (idx & 7) * 4;                             \
            cp_async16(_as + (uint32_t)(row * A_STRIDE + c) * 4,               \
                       _ga + (size_t)row * K + c);                             \
        }                                                                      \
        _Pragma("unroll")                                                      \
        for (int j = 0; j < 8; j++) {                                          \
            int idx = tid + j * 256;                                           \
            int row = idx >> 3, c = (idx & 7) * 4;                             \
            cp_async16(_bs + (uint32_t)(row * B_STRIDE + c) * 4,               \
                       _gb + (size_t)row * K + c);                             \
        }                                                                      \
        cp_commit();                                                           \
    } while (0)

    ISSUE1(0);
    ISSUE1(1);

    for (int it = 0; it < nk; it++) {
        if (it < nk - 1) cp_wait<1>(); else cp_wait<0>();
        __syncthreads();
        if (it + 2 < nk) ISSUE1(it + 2);

        const float* As = (const float*)(smem + (it % NSTG) * STAGE1_BYTES);
        const float* Bs = As + A_TILE_FLOATS;

#pragma unroll
        for (int ks = 0; ks < 4; ks++) {
            const int k0 = ks * 8;
            uint32_t a[4][4], b[8][2];
#pragma unroll
            for (int mt = 0; mt < 4; mt++) {
                int m0 = wm + mt * 16 + g;
                a[mt][0] = __float_as_uint(As[m0 * A_STRIDE + k0 + tc]);
                a[mt][1] = __float_as_uint(As[(m0 + 8) * A_STRIDE + k0 + tc]);
                a[mt][2] = __float_as_uint(As[m0 * A_STRIDE + k0 + tc + 4]);
                a[mt][3] = __float_as_uint(As[(m0 + 8) * A_STRIDE + k0 + tc + 4]);
            }
#pragma unroll
            for (int nt = 0; nt < 8; nt++) {
                int n0 = wn + nt * 8 + g;
                b[nt][0] = __float_as_uint(Bs[n0 * B_STRIDE + k0 + tc]);
                b[nt][1] = __float_as_uint(Bs[n0 * B_STRIDE + k0 + tc + 4]);
            }
#pragma unroll
            for (int mt = 0; mt < 4; mt++)
#pragma unroll
                for (int nt = 0; nt < 8; nt++)
                    mma_tf32(acc[mt][nt], a[mt], b[nt]);
        }
    }
#undef ISSUE1

    // epilogue: E = fp16(exp(alpha * S))
#pragma unroll
    for (int mt = 0; mt < 4; mt++) {
#pragma unroll
        for (int nt = 0; nt < 8; nt++) {
            int row = bm + wm + mt * 16 + g;
            int col = bn + wn + nt * 8 + 2 * tc;
            __half2 e0 = __float22half2_rn(
                make_float2(__expf(acc[mt][nt][0] * alpha), __expf(acc[mt][nt][1] * alpha)));
            __half2 e1 = __float22half2_rn(
                make_float2(__expf(acc[mt][nt][2] * alpha), __expf(acc[mt][nt][3] * alpha)));
            *(uint32_t*)&C[(size_t)row * NT + col]       = *(uint32_t*)&e0;
            *(uint32_t*)&C[(size_t)(row + 8) * NT + col] = *(uint32_t*)&e1;
        }
    }
}

// ================= GEMM 2 (fp16): O = (E V) / rowsum(E) ======================
// A = E fp16 [NT,NT] row-major; B = Vt fp16 [DV,NT] row-major (K-major).
#define BKH 64                       // k halfs per stage
#define SH 72                        // smem row stride in halfs (36 words)
#define A2_TILE_BYTES (BM * SH * 2)  // 18432
#define B2_TILE_BYTES (BN * SH * 2)  // 36864
#define STAGE2_BYTES (A2_TILE_BYTES + B2_TILE_BYTES)  // 55296
#define SMEM_G2 (NSTG * STAGE2_BYTES)

__global__ __launch_bounds__(256, 1) void gemm_pv_norm(
    const __half* __restrict__ A, const __half* __restrict__ B,
    float* __restrict__ C, size_t sA, size_t sB, size_t sC)
{
    extern __shared__ char smem[];
    __shared__ float rowinv[BM];
    const int tid = threadIdx.x;
    const int wid = tid >> 5;
    const int lane = tid & 31;
    const int g = lane >> 2;
    const int tc = lane & 3;
    const int K = NT;

    A += (size_t)blockIdx.z * sA;
    B += (size_t)blockIdx.z * sB;
    C += (size_t)blockIdx.z * sC;
    const int bm = blockIdx.y * BM;
    const int bn = blockIdx.x * BN;
    const int wm = (wid & 1) * 64;
    const int wn = (wid >> 1) * 64;

    float acc[4][8][4];
#pragma unroll
    for (int mt = 0; mt < 4; mt++)
#pragma unroll
        for (int nt = 0; nt < 8; nt++)
#pragma unroll
            for (int i = 0; i < 4; i++) acc[mt][nt][i] = 0.f;

    float rs[4][2];
#pragma unroll
    for (int mt = 0; mt < 4; mt++) { rs[mt][0] = 0.f; rs[mt][1] = 0.f; }

    const int nk = K / BKH;   // 32

#define ISSUE2(it) do {                                                        \
        int _st = (it) % NSTG;                                                 \
        uint32_t _as = smem_u32(smem) + _st * STAGE2_BYTES;                    \
        uint32_t _bs = _as + A2_TILE_BYTES;                                    \
        const __half* _ga = A + (size_t)bm * K + (size_t)(it) * BKH;           \
        const __half* _gb = B + (size_t)bn * K + (size_t)(it) * BKH;           \
        _Pragma("unroll")                                                      \
        for (int j = 0; j < 4; j++) {                                          \
            int idx = tid + j * 256;                                           \
            int row = idx >> 3, c8 = idx & 7;                                  \
            cp_async16(_as + (uint32_t)(row * SH * 2 + c8 * 16),               \
                       _ga + (size_t)row * K + c8 * 8);                        \
        }                                                                      \
        _Pragma("unroll")                                                      \
        for (int j = 0; j < 8; j++) {                                          \
            int idx = tid + j * 256;                                           \
            int row = idx >> 3, c8 = idx & 7;                                  \
            cp_async16(_bs + (uint32_t)(row * SH * 2 + c8 * 16),               \
                       _gb + (size_t)row * K + c8 * 8);                        \
        }                                                                      \
        cp_commit();                                                           \
    } while (0)

    ISSUE2(0);
    ISSUE2(1);

    for (int it = 0; it < nk; it++) {
        if (it < nk - 1) cp_wait<1>(); else cp_wait<0>();
        __syncthreads();
        if (it + 2 < nk) ISSUE2(it + 2);

        const uint32_t* Asw = (const uint32_t*)(smem + (it % NSTG) * STAGE2_BYTES);
        const uint32_t* Bsw = Asw + A2_TILE_BYTES / 4;

#pragma unroll
        for (int ks = 0; ks < 4; ks++) {          // 4 x k16 per stage
            const int kw = ks * 8;                 // word offset
            uint32_t a[4][4], b[8][2];
#pragma unroll
            for (int mt = 0; mt < 4; mt++) {
                int m0 = wm + mt * 16 + g;
                a[mt][0] = Asw[m0 * (SH / 2) + kw + tc];
                a[mt][1] = Asw[(m0 + 8) * (SH / 2) + kw + tc];
                a[mt][2] = Asw[m0 * (SH / 2) + kw + tc + 4];
                a[mt][3] = Asw[(m0 + 8) * (SH / 2) + kw + tc + 4];
            }
            if (wid < 2) {   // wn==0 warps: exact row sums of E
#pragma unroll
                for (int mt = 0; mt < 4; mt++) {
                    float2 f0 = h2f2(a[mt][0]), f2 = h2f2(a[mt][2]);
                    float2 f1 = h2f2(a[mt][1]), f3 = h2f2(a[mt][3]);
                    rs[mt][0] += (f0.x + f0.y) + (f2.x + f2.y);
                    rs[mt][1] += (f1.x + f1.y) + (f3.x + f3.y);
                }
            }
#pragma unroll
            for (int nt = 0; nt < 8; nt++) {
                int n0 = wn + nt * 8 + g;
                b[nt][0] = Bsw[n0 * (SH / 2) + kw + tc];
                b[nt][1] = Bsw[n0 * (SH / 2) + kw + tc + 4];
            }
#pragma unroll
            for (int mt = 0; mt < 4; mt++)
#pragma unroll
                for (int nt = 0; nt < 8; nt++)
                    mma_f16(acc[mt][nt], a[mt], b[nt]);
        }
    }
#undef ISSUE2

    if (wid < 2) {
#pragma unroll
        for (int mt = 0; mt < 4; mt++) {
#pragma unroll
            for (int h2 = 0; h2 < 2; h2++) {
                float s = rs[mt][h2];
                s += __shfl_xor_sync(0xffffffffu, s, 1);
                s += __shfl_xor_sync(0xffffffffu, s, 2);
                if (tc == 0) rowinv[wm + mt * 16 + g + h2 * 8] = 1.f / s;
            }
        }
    }
    __syncthreads();

#pragma unroll
    for (int mt = 0; mt < 4; mt++) {
        float inv0 = rowinv[wm + mt * 16 + g];
        float inv1 = rowinv[wm + mt * 16 + g + 8];
#pragma unroll
        for (int nt = 0; nt < 8; nt++) {
            int row = bm + wm + mt * 16 + g;
            int col = bn + wn + nt * 8 + 2 * tc;
            float2 v0 = make_float2(acc[mt][nt][0] * inv0, acc[mt][nt][1] * inv0);
            float2 v1 = make_float2(acc[mt][nt][2] * inv1, acc[mt][nt][3] * inv1);
            *(float2*)&C[(size_t)row * DV + col] = v0;
            *(float2*)&C[(size_t)(row + 8) * DV + col] = v1;
        }
    }
}

// ---------------- kernel 1: QKV projection + PReLU + per-head LN ------------
__global__ __launch_bounds__(256) void qkv_kernel(
    const float* __restrict__ x,
    const float* __restrict__ Wq, const float* __restrict__ bq, const float* __restrict__ aq,
    const float* __restrict__ gq, const float* __restrict__ betaq,
    const float* __restrict__ Wk, const float* __restrict__ bk, const float* __restrict__ ak,
    const float* __restrict__ gk, const float* __restrict__ betak,
    const float* __restrict__ Wv, const float* __restrict__ bv, const float* __restrict__ av,
    const float* __restrict__ gv, const float* __restrict__ betav)
{
    __shared__ float sWq[NH * NHC * NC];
    __shared__ float sWk[NH * NHC * NC];
    __shared__ float sWv[NH * NVC * NC];

    int tid = threadIdx.y * 64 + threadIdx.x;
    for (int i = tid; i < NH * NHC * NC; i += 256) { sWq[i] = Wq[i]; sWk[i] = Wk[i]; }
    for (int i = tid; i < NH * NVC * NC; i += 256) { sWv[i] = Wv[i]; }
    __syncthreads();

    int f = threadIdx.x;
    int t = blockIdx.x * 4 + threadIdx.y;
    int b = blockIdx.y;

    const float* xp = x + ((size_t)b * NC * NT + t) * NF + f;

    float xr[NC];
#pragma unroll
    for (int c = 0; c < NC; c++) xr[c] = xp[(size_t)c * NT * NF];

    for (int h = 0; h < NH; h++) {
        float q[NHC], k[NHC], v[NVC];
#pragma unroll
        for (int j = 0; j < NHC; j++) { q[j] = 0.f; k[j] = 0.f; }
#pragma unroll
        for (int j = 0; j < NVC; j++) v[j] = 0.f;

#pragma unroll 4
        for (int c0 = 0; c0 < NC; c0 += 4) {
#pragma unroll
            for (int j = 0; j < NHC; j++) {
                float4 w = *(const float4*)&sWq[(h * NHC + j) * NC + c0];
                q[j] += w.x * xr[c0] + w.y * xr[c0 + 1] + w.z * xr[c0 + 2] + w.w * xr[c0 + 3];
            }
#pragma unroll
            for (int j = 0; j < NHC; j++) {
                float4 w = *(const float4*)&sWk[(h * NHC + j) * NC + c0];
                k[j] += w.x * xr[c0] + w.y * xr[c0 + 1] + w.z * xr[c0 + 2] + w.w * xr[c0 + 3];
            }
#pragma unroll
            for (int j = 0; j < NVC; j++) {
                float4 w = *(const float4*)&sWv[(h * NVC + j) * NC + c0];
                v[j] += w.x * xr[c0] + w.y * xr[c0 + 1] + w.z * xr[c0 + 2] + w.w * xr[c0 + 3];
            }
        }
        {
            float a = aq[h], mu = 0.f;
#pragma unroll
            for (int j = 0; j < NHC; j++) {
                float y = q[j] + bq[h * NHC + j];
                y = (y >= 0.f) ? y : a * y; q[j] = y; mu += y;
            }
            mu *= (1.f / NHC);
            float var = 0.f;
#pragma unroll
            for (int j = 0; j < NHC; j++) { float d = q[j] - mu; var += d * d; }
            float r = rsqrtf(var * (1.f / NHC) + EPSV);
#pragma unroll
            for (int j = 0; j < NHC; j++) {
                float o = (q[j] - mu) * r * gq[h * NHC + j] + betaq[h * NHC + j];
                g_Q[((size_t)(h * NB + b) * NT + t) * DQK + j * NF + f] = to_tf32(o);
            }
        }
        {
            float a = ak[h], mu = 0.f;
#pragma unroll
            for (int j = 0; j < NHC; j++) {
                float y = k[j] + bk[h * NHC + j];
                y = (y >= 0.f) ? y : a * y; k[j] = y; mu += y;
            }
            mu *= (1.f / NHC);
            float var = 0.f;
#pragma unroll
            for (int j = 0; j < NHC; j++) { float d = k[j] - mu; var += d * d; }
            float r = rsqrtf(var * (1.f / NHC) + EPSV);
#pragma unroll
            for (int j = 0; j < NHC; j++) {
                float o = (k[j] - mu) * r * gk[h * NHC + j] + betak[h * NHC + j];
                g_K[((size_t)(h * NB + b) * NT + t) * DQK + j * NF + f] = to_tf32(o);
            }
        }
        {
            float a = av[h], mu = 0.f;
#pragma unroll
            for (int j = 0; j < NVC; j++) {
                float y = v[j] + bv[h * NVC + j];
                y = (y >= 0.f) ? y : a * y; v[j] = y; mu += y;
            }
            mu *= (1.f / NVC);
            float var = 0.f;
#pragma unroll
            for (int j = 0; j < NVC; j++) { float d = v[j] - mu; var += d * d; }
            float r = rsqrtf(var * (1.f / NVC) + EPSV);
#pragma unroll
            for (int j = 0; j < NVC; j++) {
                float o = (v[j] - mu) * r * gv[h * NVC + j] + betav[h * NVC + j];
                g_V[((size_t)(h * NB + b) * NT + t) * DV + j * NF + f] = __float2half_rn(o);
            }
        }
    }
}

// ---------------- transpose V (fp16): [t][dv] -> [dv][t] per z ----------------
__global__ __launch_bounds__(256) void transpose_v()
{
    __shared__ __half tile[32][33];
    int bt = blockIdx.x * 32, bd = blockIdx.y * 32;
    size_t base = (size_t)blockIdx.z * NT * DV;
    int tx = threadIdx.x, ty = threadIdx.y;
#pragma unroll
    for (int j = 0; j < 4; j++)
        tile[ty + j * 8][tx] = g_V[base + (size_t)(bt + ty + j * 8) * DV + bd + tx];
    __syncthreads();
#pragma unroll
    for (int j = 0; j < 4; j++)
        g_Vt[base + (size_t)(bd + ty + j * 8) * NT + bt + tx] = tile[tx][ty + j * 8];
}

// ---------------- output projection + PReLU + LN + residual ------------------
// block = 256 threads = 64 f-positions x 4 channel-groups; one block per (t,b).
__global__ __launch_bounds__(256) void out_kernel(
    const float* __restrict__ x,
    const float* __restrict__ Wp, const float* __restrict__ bp, const float* __restrict__ ap,
    const float* __restrict__ gp, const float* __restrict__ betap,
    float* __restrict__ out)
{
    __shared__ float sWt[NC * 68];   // [c][o], stride 68
    __shared__ float sOg[NC * 68];   // [c][f], stride 68

    const int tid = threadIdx.x;
    const int t = blockIdx.x;
    const int b = blockIdx.y;

    // Wp[o][c] -> sWt[c][o]
    for (int i = tid; i < NC * NC; i += 256) {
        int o = i >> 6, c = i & 63;
        sWt[c * 68 + o] = Wp[i];
    }
    // O gather: heads are contiguous 1024-float segments for this (t,b)
#pragma unroll
    for (int h = 0; h < NH; h++) {
        const float4* src = (const float4*)&g_O[((size_t)(h * NB + b) * NT + t) * DV];
        float4 val = src[tid];
        int vc = tid >> 4;
        int f0 = (tid & 15) * 4;
        *(float4*)&sOg[(h * 16 + vc) * 68 + f0] = val;
    }
    __syncthreads();

    const int j = tid & 3;        // channel group
    const int f = tid >> 2;       // freq position
    const int o0 = 16 * j;

    float acc[16];
#pragma unroll
    for (int i = 0; i < 16; i++) acc[i] = 0.f;

#pragma unroll 8
    for (int c = 0; c < NC; c++) {
        float og = sOg[c * 68 + f];
        float4 w0 = *(const float4*)&sWt[c * 68 + o0];
        float4 w1 = *(const float4*)&sWt[c * 68 + o0 + 4];
        float4 w2 = *(const float4*)&sWt[c * 68 + o0 + 8];
        float4 w3 = *(const float4*)&sWt[c * 68 + o0 + 12];
        acc[0] += w0.x * og;  acc[1] += w0.y * og;  acc[2] += w0.z * og;  acc[3] += w0.w * og;
        acc[4] += w1.x * og;  acc[5] += w1.y * og;  acc[6] += w1.z * og;  acc[7] += w1.w * og;
        acc[8] += w2.x * og;  acc[9] += w2.y * og;  acc[10] += w2.z * og; acc[11] += w2.w * og;
        acc[12] += w3.x * og; acc[13] += w3.y * og; acc[14] += w3.z * og; acc[15] += w3.w * og;
    }

    float a = ap[0];
    float s1 = 0.f, s2 = 0.f;
#pragma unroll
    for (int i = 0; i < 16; i++) {
        float y = acc[i] + bp[o0 + i];
        y = (y >= 0.f) ? y : a * y;
        acc[i] = y;
        s1 += y; s2 += y * y;
    }
    s1 += __shfl_xor_sync(0xffffffffu, s1, 1);
    s1 += __shfl_xor_sync(0xffffffffu, s1, 2);
    s2 += __shfl_xor_sync(0xffffffffu, s2, 1);
    s2 += __shfl_xor_sync(0xffffffffu, s2, 2);
    float mu = s1 * (1.f / NC);
    float var = s2 * (1.f / NC) - mu * mu;
    float r = rsqrtf(var + EPSV);

#pragma unroll
    for (int i = 0; i < 16; i++) {
        int o = o0 + i;
        size_t idx = (((size_t)b * NC + o) * NT + t) * NF + f;
        out[idx] = (acc[i] - mu) * r * gp[o] + betap[o] + x[idx];
    }
}

// ---------------- launch ------------------------------------------------------
extern "C" void kernel_launch(void* const* d_in, const int* in_sizes, int n_in,
                              void* d_out, int out_size)
{
    const float* x     = (const float*)d_in[0];
    const float* Wq    = (const float*)d_in[1];
    const float* bq    = (const float*)d_in[2];
    const float* aq    = (const float*)d_in[3];
    const float* gq    = (const float*)d_in[4];
    const float* betaq = (const float*)d_in[5];
    const float* Wk    = (const float*)d_in[6];
    const float* bk    = (const float*)d_in[7];
    const float* ak    = (const float*)d_in[8];
    const float* gk    = (const float*)d_in[9];
    const float* betak = (const float*)d_in[10];
    const float* Wv    = (const float*)d_in[11];
    const float* bv    = (const float*)d_in[12];
    const float* av    = (const float*)d_in[13];
    const float* gv    = (const float*)d_in[14];
    const float* betav = (const float*)d_in[15];
    const float* Wp    = (const float*)d_in[16];
    const float* bp    = (const float*)d_in[17];
    const float* ap    = (const float*)d_in[18];
    const float* gp    = (const float*)d_in[19];
    const float* betap = (const float*)d_in[20];
    float* out = (float*)d_out;

    float *pQ, *pK, *pO;
    __half *pV, *pVt, *pE;
    cudaGetSymbolAddress((void**)&pQ, g_Q);
    cudaGetSymbolAddress((void**)&pK, g_K);
    cudaGetSymbolAddress((void**)&pV, g_V);
    cudaGetSymbolAddress((void**)&pVt, g_Vt);
    cudaGetSymbolAddress((void**)&pE, g_E);
    cudaGetSymbolAddress((void**)&pO, g_O);

    cudaFuncSetAttribute(gemm_qk_exp, cudaFuncAttributeMaxDynamicSharedMemorySize, SMEM_G1);
    cudaFuncSetAttribute(gemm_pv_norm, cudaFuncAttributeMaxDynamicSharedMemorySize, SMEM_G2);

    // 1) QKV projections (Q,K tf32 fp32; V fp16)
    qkv_kernel<<<dim3(NT / 4, NB), dim3(64, 4)>>>(
        x, Wq, bq, aq, gq, betaq, Wk, bk, ak, gk, betak, Wv, bv, av, gv, betav);

    // 2) V transpose (fp16): [t][dv] -> [dv][t]
    transpose_v<<<dim3(NT / 32, DV / 32, NHB), dim3(32, 8)>>>();

    // 3) E = fp16(exp((1/16) Q K^T))
    gemm_qk_exp<<<dim3(NT / BN, NT / BM, NHB), 256, SMEM_G1>>>(
        pQ, pK, pE, 0.0625f,
        (size_t)NT * DQK, (size_t)NT * DQK, (size_t)NT * NT);

    // 4) O = (E V) / rowsum(E)   (fp16 mma, in-loop row sums)
    gemm_pv_norm<<<dim3(DV / BN, NT / BM, NHB), 256, SMEM_G2>>>(
        pE, pVt, pO,
        (size_t)NT * NT, (size_t)DV * NT, (size_t)NT * DV);

    // 5) output projection + LN + residual
    out_kernel<<<dim3(NT, NB), 256>>>(
        x, Wp, bp, ap, gp, betap, out);
}

// round 8
// speedup vs baseline: 1.3792x; 1.3792x over previous
#include <cuda_runtime.h>
#include <cuda_fp16.h>
#include <cstdint>
#include <cstddef>

#define EPSV 1e-5f

// problem dims (fixed)
#define NB 2
#define NC 64
#define NT 2048
#define NF 64
#define NH 4
#define NHC 4
#define NVC 16
#define DQK 256   // NHC*NF
#define DV  1024  // NVC*NF
#define NHB 8     // NH*NB

// ---------------- scratch (device globals; no allocations allowed) ----------
__device__ __half g_Q[(size_t)NHB * NT * DQK];   // 8 MB
__device__ __half g_K[(size_t)NHB * NT * DQK];   // 8 MB
__device__ __half g_V[(size_t)NHB * NT * DV];    // 32 MB
__device__ __half g_Vt[(size_t)NHB * DV * NT];   // 32 MB  V^T per z: [dv][t]
__device__ __half g_E[(size_t)NHB * NT * NT];    // 64 MB  exp(alpha*S)
__device__ float  g_O[(size_t)NHB * NT * DV];    // 64 MB

// ---------------- helpers ----------------------------------------------------
__device__ __forceinline__ uint32_t smem_u32(const void* p) {
    uint32_t a;
    asm("{ .reg .u64 t; cvta.to.shared.u64 t, %1; cvt.u32.u64 %0, t; }" : "=r"(a) : "l"(p));
    return a;
}
__device__ __forceinline__ void cp_async16(uint32_t dst, const void* src) {
    asm volatile("cp.async.cg.shared.global [%0], [%1], 16;" :: "r"(dst), "l"(src) : "memory");
}
__device__ __forceinline__ void cp_commit() { asm volatile("cp.async.commit_group;" ::: "memory"); }
template <int N> __device__ __forceinline__ void cp_wait() {
    asm volatile("cp.async.wait_group %0;" :: "n"(N) : "memory");
}
__device__ __forceinline__ void mma_f16(float* c, const uint32_t* a, const uint32_t* b) {
    asm volatile(
        "mma.sync.aligned.m16n8k16.row.col.f32.f16.f16.f32 "
        "{%0,%1,%2,%3}, {%4,%5,%6,%7}, {%8,%9}, {%0,%1,%2,%3};"
        : "+f"(c[0]), "+f"(c[1]), "+f"(c[2]), "+f"(c[3])
        : "r"(a[0]), "r"(a[1]), "r"(a[2]), "r"(a[3]), "r"(b[0]), "r"(b[1]));
}
__device__ __forceinline__ float2 h2f2(uint32_t u) {
    return __half22float2(*reinterpret_cast<__half2*>(&u));
}

// common tile geometry (both GEMMs)
#define BM 128
#define BN 256
#define BKH 64                       // k halfs per stage
#define SH 72                        // smem row stride in halfs (36 words)
#define A2_TILE_BYTES (BM * SH * 2)  // 18432
#define B2_TILE_BYTES (BN * SH * 2)  // 36864
#define STAGE_BYTES (A2_TILE_BYTES + B2_TILE_BYTES)  // 55296
#define NSTG 3
#define SMEM_GEMM (NSTG * STAGE_BYTES)

#define ISSUE_F16(it, Kd) do {                                                  \
        int _st = (it) % NSTG;                                                  \
        uint32_t _as = smem_u32(smem) + _st * STAGE_BYTES;                      \
        uint32_t _bs = _as + A2_TILE_BYTES;                                     \
        const __half* _ga = A + (size_t)bm * (Kd) + (size_t)(it) * BKH;         \
        const __half* _gb = B + (size_t)bn * (Kd) + (size_t)(it) * BKH;         \
        _Pragma("unroll")                                                       \
        for (int j = 0; j < 4; j++) {                                           \
            int idx = tid + j * 256;                                            \
            int row = idx >> 3, c8 = idx & 7;                                   \
            cp_async16(_as + (uint32_t)(row * SH * 2 + c8 * 16),                \
                       _ga + (size_t)row * (Kd) + c8 * 8);                      \
        }                                                                       \
        _Pragma("unroll")                                                       \
        for (int j = 0; j < 8; j++) {                                           \
            int idx = tid + j * 256;                                            \
            int row = idx >> 3, c8 = idx & 7;                                   \
            cp_async16(_bs + (uint32_t)(row * SH * 2 + c8 * 16),                \
                       _gb + (size_t)row * (Kd) + c8 * 8);                      \
        }                                                                       \
        cp_commit();                                                            \
    } while (0)

// ================= GEMM 1 (fp16): E = fp16(exp(alpha * Q K^T)) ===============
__global__ __launch_bounds__(256, 1) void gemm_qk_exp(
    const __half* __restrict__ A, const __half* __restrict__ B, __half* __restrict__ C,
    float alpha, size_t sA, size_t sB, size_t sC)
{
    extern __shared__ char smem[];
    const int tid = threadIdx.x;
    const int wid = tid >> 5;
    const int lane = tid & 31;
    const int g = lane >> 2;
    const int tc = lane & 3;

    A += (size_t)blockIdx.z * sA;
    B += (size_t)blockIdx.z * sB;
    C += (size_t)blockIdx.z * sC;
    const int bm = blockIdx.y * BM;
    const int bn = blockIdx.x * BN;
    const int wm = (wid & 1) * 64;
    const int wn = (wid >> 1) * 64;

    float acc[4][8][4];
#pragma unroll
    for (int mt = 0; mt < 4; mt++)
#pragma unroll
        for (int nt = 0; nt < 8; nt++)
#pragma unroll
            for (int i = 0; i < 4; i++) acc[mt][nt][i] = 0.f;

    const int nk = DQK / BKH;   // 4

    ISSUE_F16(0, DQK);
    ISSUE_F16(1, DQK);

    for (int it = 0; it < nk; it++) {
        if (it < nk - 1) cp_wait<1>(); else cp_wait<0>();
        __syncthreads();
        if (it + 2 < nk) ISSUE_F16(it + 2, DQK);

        const uint32_t* Asw = (const uint32_t*)(smem + (it % NSTG) * STAGE_BYTES);
        const uint32_t* Bsw = Asw + A2_TILE_BYTES / 4;

#pragma unroll
        for (int ks = 0; ks < 4; ks++) {
            const int kw = ks * 8;
            uint32_t a[4][4], b[8][2];
#pragma unroll
            for (int mt = 0; mt < 4; mt++) {
                int m0 = wm + mt * 16 + g;
                a[mt][0] = Asw[m0 * (SH / 2) + kw + tc];
                a[mt][1] = Asw[(m0 + 8) * (SH / 2) + kw + tc];
                a[mt][2] = Asw[m0 * (SH / 2) + kw + tc + 4];
                a[mt][3] = Asw[(m0 + 8) * (SH / 2) + kw + tc + 4];
            }
#pragma unroll
            for (int nt = 0; nt < 8; nt++) {
                int n0 = wn + nt * 8 + g;
                b[nt][0] = Bsw[n0 * (SH / 2) + kw + tc];
                b[nt][1] = Bsw[n0 * (SH / 2) + kw + tc + 4];
            }
#pragma unroll
            for (int mt = 0; mt < 4; mt++)
#pragma unroll
                for (int nt = 0; nt < 8; nt++)
                    mma_f16(acc[mt][nt], a[mt], b[nt]);
        }
    }

    // epilogue: E = fp16(exp(alpha * S))
#pragma unroll
    for (int mt = 0; mt < 4; mt++) {
#pragma unroll
        for (int nt = 0; nt < 8; nt++) {
            int row = bm + wm + mt * 16 + g;
            int col = bn + wn + nt * 8 + 2 * tc;
            __half2 e0 = __float22half2_rn(
                make_float2(__expf(acc[mt][nt][0] * alpha), __expf(acc[mt][nt][1] * alpha)));
            __half2 e1 = __float22half2_rn(
                make_float2(__expf(acc[mt][nt][2] * alpha), __expf(acc[mt][nt][3] * alpha)));
            *(uint32_t*)&C[(size_t)row * NT + col]       = *(uint32_t*)&e0;
            *(uint32_t*)&C[(size_t)(row + 8) * NT + col] = *(uint32_t*)&e1;
        }
    }
}

// ================= GEMM 2 (fp16): O = (E V) / rowsum(E) ======================
__global__ __launch_bounds__(256, 1) void gemm_pv_norm(
    const __half* __restrict__ A, const __half* __restrict__ B,
    float* __restrict__ C, size_t sA, size_t sB, size_t sC)
{
    extern __shared__ char smem[];
    __shared__ float rowinv[BM];
    const int tid = threadIdx.x;
    const int wid = tid >> 5;
    const int lane = tid & 31;
    const int g = lane >> 2;
    const int tc = lane & 3;

    A += (size_t)blockIdx.z * sA;
    B += (size_t)blockIdx.z * sB;
    C += (size_t)blockIdx.z * sC;
    const int bm = blockIdx.y * BM;
    const int bn = blockIdx.x * BN;
    const int wm = (wid & 1) * 64;
    const int wn = (wid >> 1) * 64;

    float acc[4][8][4];
#pragma unroll
    for (int mt = 0; mt < 4; mt++)
#pragma unroll
        for (int nt = 0; nt < 8; nt++)
#pragma unroll
            for (int i = 0; i < 4; i++) acc[mt][nt][i] = 0.f;

    float rs[4][2];
#pragma unroll
    for (int mt = 0; mt < 4; mt++) { rs[mt][0] = 0.f; rs[mt][1] = 0.f; }

    const int nk = NT / BKH;   // 32

    ISSUE_F16(0, NT);
    ISSUE_F16(1, NT);

    for (int it = 0; it < nk; it++) {
        if (it < nk - 1) cp_wait<1>(); else cp_wait<0>();
        __syncthreads();
        if (it + 2 < nk) ISSUE_F16(it + 2, NT);

        const uint32_t* Asw = (const uint32_t*)(smem + (it % NSTG) * STAGE_BYTES);
        const uint32_t* Bsw = Asw + A2_TILE_BYTES / 4;

#pragma unroll
        for (int ks = 0; ks < 4; ks++) {
            const int kw = ks * 8;
            uint32_t a[4][4], b[8][2];
#pragma unroll
            for (int mt = 0; mt < 4; mt++) {
                int m0 = wm + mt * 16 + g;
                a[mt][0] = Asw[m0 * (SH / 2) + kw + tc];
                a[mt][1] = Asw[(m0 + 8) * (SH / 2) + kw + tc];
                a[mt][2] = Asw[m0 * (SH / 2) + kw + tc + 4];
                a[mt][3] = Asw[(m0 + 8) * (SH / 2) + kw + tc + 4];
            }
            if (wid < 2) {   // wn==0 warps: exact row sums of E
#pragma unroll
                for (int mt = 0; mt < 4; mt++) {
                    float2 f0 = h2f2(a[mt][0]), f2 = h2f2(a[mt][2]);
                    float2 f1 = h2f2(a[mt][1]), f3 = h2f2(a[mt][3]);
                    rs[mt][0] += (f0.x + f0.y) + (f2.x + f2.y);
                    rs[mt][1] += (f1.x + f1.y) + (f3.x + f3.y);
                }
            }
#pragma unroll
            for (int nt = 0; nt < 8; nt++) {
                int n0 = wn + nt * 8 + g;
                b[nt][0] = Bsw[n0 * (SH / 2) + kw + tc];
                b[nt][1] = Bsw[n0 * (SH / 2) + kw + tc + 4];
            }
#pragma unroll
            for (int mt = 0; mt < 4; mt++)
#pragma unroll
                for (int nt = 0; nt < 8; nt++)
                    mma_f16(acc[mt][nt], a[mt], b[nt]);
        }
    }

    if (wid < 2) {
#pragma unroll
        for (int mt = 0; mt < 4; mt++) {
#pragma unroll
            for (int h2 = 0; h2 < 2; h2++) {
                float s = rs[mt][h2];
                s += __shfl_xor_sync(0xffffffffu, s, 1);
                s += __shfl_xor_sync(0xffffffffu, s, 2);
                if (tc == 0) rowinv[wm + mt * 16 + g + h2 * 8] = 1.f / s;
            }
        }
    }
    __syncthreads();

#pragma unroll
    for (int mt = 0; mt < 4; mt++) {
        float inv0 = rowinv[wm + mt * 16 + g];
        float inv1 = rowinv[wm + mt * 16 + g + 8];
#pragma unroll
        for (int nt = 0; nt < 8; nt++) {
            int row = bm + wm + mt * 16 + g;
            int col = bn + wn + nt * 8 + 2 * tc;
            float2 v0 = make_float2(acc[mt][nt][0] * inv0, acc[mt][nt][1] * inv0);
            float2 v1 = make_float2(acc[mt][nt][2] * inv1, acc[mt][nt][3] * inv1);
            *(float2*)&C[(size_t)row * DV + col] = v0;
            *(float2*)&C[(size_t)(row + 8) * DV + col] = v1;
        }
    }
}

// ---------------- kernel 1: QKV projection + PReLU + per-head LN ------------
__global__ __launch_bounds__(256) void qkv_kernel(
    const float* __restrict__ x,
    const float* __restrict__ Wq, const float* __restrict__ bq, const float* __restrict__ aq,
    const float* __restrict__ gq, const float* __restrict__ betaq,
    const float* __restrict__ Wk, const float* __restrict__ bk, const float* __restrict__ ak,
    const float* __restrict__ gk, const float* __restrict__ betak,
    const float* __restrict__ Wv, const float* __restrict__ bv, const float* __restrict__ av,
    const float* __restrict__ gv, const float* __restrict__ betav)
{
    __shared__ float sWq[NH * NHC * NC];
    __shared__ float sWk[NH * NHC * NC];
    __shared__ float sWv[NH * NVC * NC];

    int tid = threadIdx.y * 64 + threadIdx.x;
    for (int i = tid; i < NH * NHC * NC; i += 256) { sWq[i] = Wq[i]; sWk[i] = Wk[i]; }
    for (int i = tid; i < NH * NVC * NC; i += 256) { sWv[i] = Wv[i]; }
    __syncthreads();

    int f = threadIdx.x;
    int t = blockIdx.x * 4 + threadIdx.y;
    int b = blockIdx.y;

    const float* xp = x + ((size_t)b * NC * NT + t) * NF + f;

    float xr[NC];
#pragma unroll
    for (int c = 0; c < NC; c++) xr[c] = xp[(size_t)c * NT * NF];

    for (int h = 0; h < NH; h++) {
        float q[NHC], k[NHC], v[NVC];
#pragma unroll
        for (int j = 0; j < NHC; j++) { q[j] = 0.f; k[j] = 0.f; }
#pragma unroll
        for (int j = 0; j < NVC; j++) v[j] = 0.f;

#pragma unroll 4
        for (int c0 = 0; c0 < NC; c0 += 4) {
#pragma unroll
            for (int j = 0; j < NHC; j++) {
                float4 w = *(const float4*)&sWq[(h * NHC + j) * NC + c0];
                q[j] += w.x * xr[c0] + w.y * xr[c0 + 1] + w.z * xr[c0 + 2] + w.w * xr[c0 + 3];
            }
#pragma unroll
            for (int j = 0; j < NHC; j++) {
                float4 w = *(const float4*)&sWk[(h * NHC + j) * NC + c0];
                k[j] += w.x * xr[c0] + w.y * xr[c0 + 1] + w.z * xr[c0 + 2] + w.w * xr[c0 + 3];
            }
#pragma unroll
            for (int j = 0; j < NVC; j++) {
                float4 w = *(const float4*)&sWv[(h * NVC + j) * NC + c0];
                v[j] += w.x * xr[c0] + w.y * xr[c0 + 1] + w.z * xr[c0 + 2] + w.w * xr[c0 + 3];
            }
        }
        {
            float a = aq[h], mu = 0.f;
#pragma unroll
            for (int j = 0; j < NHC; j++) {
                float y = q[j] + bq[h * NHC + j];
                y = (y >= 0.f) ? y : a * y; q[j] = y; mu += y;
            }
            mu *= (1.f / NHC);
            float var = 0.f;
#pragma unroll
            for (int j = 0; j < NHC; j++) { float d = q[j] - mu; var += d * d; }
            float r = rsqrtf(var * (1.f / NHC) + EPSV);
#pragma unroll
            for (int j = 0; j < NHC; j++) {
                float o = (q[j] - mu) * r * gq[h * NHC + j] + betaq[h * NHC + j];
                g_Q[((size_t)(h * NB + b) * NT + t) * DQK + j * NF + f] = __float2half_rn(o);
            }
        }
        {
            float a = ak[h], mu = 0.f;
#pragma unroll
            for (int j = 0; j < NHC; j++) {
                float y = k[j] + bk[h * NHC + j];
                y = (y >= 0.f) ? y : a * y; k[j] = y; mu += y;
            }
            mu *= (1.f / NHC);
            float var = 0.f;
#pragma unroll
            for (int j = 0; j < NHC; j++) { float d = k[j] - mu; var += d * d; }
            float r = rsqrtf(var * (1.f / NHC) + EPSV);
#pragma unroll
            for (int j = 0; j < NHC; j++) {
                float o = (k[j] - mu) * r * gk[h * NHC + j] + betak[h * NHC + j];
                g_K[((size_t)(h * NB + b) * NT + t) * DQK + j * NF + f] = __float2half_rn(o);
            }
        }
        {
            float a = av[h], mu = 0.f;
#pragma unroll
            for (int j = 0; j < NVC; j++) {
                float y = v[j] + bv[h * NVC + j];
                y = (y >= 0.f) ? y : a * y; v[j] = y; mu += y;
            }
            mu *= (1.f / NVC);
            float var = 0.f;
#pragma unroll
            for (int j = 0; j < NVC; j++) { float d = v[j] - mu; var += d * d; }
            float r = rsqrtf(var * (1.f / NVC) + EPSV);
#pragma unroll
            for (int j = 0; j < NVC; j++) {
                float o = (v[j] - mu) * r * gv[h * NVC + j] + betav[h * NVC + j];
                g_V[((size_t)(h * NB + b) * NT + t) * DV + j * NF + f] = __float2half_rn(o);
            }
        }
    }
}

// ---------------- transpose V (fp16): [t][dv] -> [dv][t] per z ----------------
__global__ __launch_bounds__(256) void transpose_v()
{
    __shared__ __half tile[32][33];
    int bt = blockIdx.x * 32, bd = blockIdx.y * 32;
    size_t base = (size_t)blockIdx.z * NT * DV;
    int tx = threadIdx.x, ty = threadIdx.y;
#pragma unroll
    for (int j = 0; j < 4; j++)
        tile[ty + j * 8][tx] = g_V[base + (size_t)(bt + ty + j * 8) * DV + bd + tx];
    __syncthreads();
#pragma unroll
    for (int j = 0; j < 4; j++)
        g_Vt[base + (size_t)(bd + ty + j * 8) * NT + bt + tx] = tile[tx][ty + j * 8];
}

// ---------------- output projection + PReLU + LN + residual ------------------
// block = 256 = 4 o-groups (j=tid>>6) x 64 f (tid&63); one block per (t,b).
__global__ __launch_bounds__(256) void out_kernel(
    const float* __restrict__ x,
    const float* __restrict__ Wp, const float* __restrict__ bp, const float* __restrict__ ap,
    const float* __restrict__ gp, const float* __restrict__ betap,
    float* __restrict__ out)
{
    __shared__ float sWt[NC * 68];     // [c][o]
    __shared__ float sOg[NC * 68];     // [c][f]
    __shared__ float sred1[4][64];
    __shared__ float sred2[4][64];

    const int tid = threadIdx.x;
    const int t = blockIdx.x;
    const int b = blockIdx.y;

    // Wp[o][c] -> sWt[c][o]
    for (int i = tid; i < NC * NC; i += 256) {
        int o = i >> 6, c = i & 63;
        sWt[c * 68 + o] = Wp[i];
    }
    // O gather: heads are contiguous 1024-float segments for this (t,b)
#pragma unroll
    for (int h = 0; h < NH; h++) {
        const float4* src = (const float4*)&g_O[((size_t)(h * NB + b) * NT + t) * DV];
        float4 val = src[tid];
        int vc = tid >> 4;
        int f0 = (tid & 15) * 4;
        *(float4*)&sOg[(h * 16 + vc) * 68 + f0] = val;
    }
    __syncthreads();

    const int j = tid >> 6;       // o-group (warp-uniform)
    const int f = tid & 63;       // freq position (consecutive in warp)
    const int o0 = 16 * j;

    float acc[16];
#pragma unroll
    for (int i = 0; i < 16; i++) acc[i] = 0.f;

#pragma unroll 8
    for (int c = 0; c < NC; c++) {
        float og = sOg[c * 68 + f];
        float4 w0 = *(const float4*)&sWt[c * 68 + o0];
        float4 w1 = *(const float4*)&sWt[c * 68 + o0 + 4];
        float4 w2 = *(const float4*)&sWt[c * 68 + o0 + 8];
        float4 w3 = *(const float4*)&sWt[c * 68 + o0 + 12];
        acc[0] += w0.x * og;  acc[1] += w0.y * og;  acc[2] += w0.z * og;  acc[3] += w0.w * og;
        acc[4] += w1.x * og;  acc[5] += w1.y * og;  acc[6] += w1.z * og;  acc[7] += w1.w * og;
        acc[8] += w2.x * og;  acc[9] += w2.y * og;  acc[10] += w2.z * og; acc[11] += w2.w * og;
        acc[12] += w3.x * og; acc[13] += w3.y * og; acc[14] += w3.z * og; acc[15] += w3.w * og;
    }

    float a = ap[0];
    float s1 = 0.f, s2 = 0.f;
#pragma unroll
    for (int i = 0; i < 16; i++) {
        float y = acc[i] + bp[o0 + i];
        y = (y >= 0.f) ? y : a * y;
        acc[i] = y;
        s1 += y; s2 += y * y;
    }
    sred1[j][f] = s1;
    sred2[j][f] = s2;
    __syncthreads();
    s1 = sred1[0][f] + sred1[1][f] + sred1[2][f] + sred1[3][f];
    s2 = sred2[0][f] + sred2[1][f] + sred2[2][f] + sred2[3][f];
    float mu = s1 * (1.f / NC);
    float var = s2 * (1.f / NC) - mu * mu;
    float r = rsqrtf(var + EPSV);

#pragma unroll
    for (int i = 0; i < 16; i++) {
        int o = o0 + i;
        size_t idx = (((size_t)b * NC + o) * NT + t) * NF + f;
        out[idx] = (acc[i] - mu) * r * gp[o] + betap[o] + x[idx];
    }
}

// ---------------- launch ------------------------------------------------------
extern "C" void kernel_launch(void* const* d_in, const int* in_sizes, int n_in,
                              void* d_out, int out_size)
{
    const float* x     = (const float*)d_in[0];
    const float* Wq    = (const float*)d_in[1];
    const float* bq    = (const float*)d_in[2];
    const float* aq    = (const float*)d_in[3];
    const float* gq    = (const float*)d_in[4];
    const float* betaq = (const float*)d_in[5];
    const float* Wk    = (const float*)d_in[6];
    const float* bk    = (const float*)d_in[7];
    const float* ak    = (const float*)d_in[8];
    const float* gk    = (const float*)d_in[9];
    const float* betak = (const float*)d_in[10];
    const float* Wv    = (const float*)d_in[11];
    const float* bv    = (const float*)d_in[12];
    const float* av    = (const float*)d_in[13];
    const float* gv    = (const float*)d_in[14];
    const float* betav = (const float*)d_in[15];
    const float* Wp    = (const float*)d_in[16];
    const float* bp    = (const float*)d_in[17];
    const float* ap    = (const float*)d_in[18];
    const float* gp    = (const float*)d_in[19];
    const float* betap = (const float*)d_in[20];
    float* out = (float*)d_out;

    float* pO;
    __half *pQ, *pK, *pV, *pVt, *pE;
    cudaGetSymbolAddress((void**)&pQ, g_Q);
    cudaGetSymbolAddress((void**)&pK, g_K);
    cudaGetSymbolAddress((void**)&pV, g_V);
    cudaGetSymbolAddress((void**)&pVt, g_Vt);
    cudaGetSymbolAddress((void**)&pE, g_E);
    cudaGetSymbolAddress((void**)&pO, g_O);

    cudaFuncSetAttribute(gemm_qk_exp, cudaFuncAttributeMaxDynamicSharedMemorySize, SMEM_GEMM);
    cudaFuncSetAttribute(gemm_pv_norm, cudaFuncAttributeMaxDynamicSharedMemorySize, SMEM_GEMM);

    // 1) QKV projections (Q,K,V fp16)
    qkv_kernel<<<dim3(NT / 4, NB), dim3(64, 4)>>>(
        x, Wq, bq, aq, gq, betaq, Wk, bk, ak, gk, betak, Wv, bv, av, gv, betav);

    // 2) V transpose (fp16): [t][dv] -> [dv][t]
    transpose_v<<<dim3(NT / 32, DV / 32, NHB), dim3(32, 8)>>>();

    // 3) E = fp16(exp((1/16) Q K^T))   (fp16 mma)
    gemm_qk_exp<<<dim3(NT / BN, NT / BM, NHB), 256, SMEM_GEMM>>>(
        pQ, pK, pE, 0.0625f,
        (size_t)NT * DQK, (size_t)NT * DQK, (size_t)NT * NT);

    // 4) O = (E V) / rowsum(E)   (fp16 mma, in-loop row sums)
    gemm_pv_norm<<<dim3(DV / BN, NT / BM, NHB), 256, SMEM_GEMM>>>(
        pE, pVt, pO,
        (size_t)NT * NT, (size_t)DV * NT, (size_t)NT * DV);

    // 5) output projection + LN + residual
    out_kernel<<<dim3(NT, NB), 256>>>(
        x, Wp, bp, ap, gp, betap, out);
}

// round 9
// speedup vs baseline: 1.4242x; 1.0326x over previous
#include <cuda_runtime.h>
#include <cuda_fp16.h>
#include <cstdint>
#include <cstddef>

#define EPSV 1e-5f

// problem dims (fixed)
#define NB 2
#define NC 64
#define NT 2048
#define NF 64
#define NH 4
#define NHC 4
#define NVC 16
#define DQK 256   // NHC*NF
#define DV  1024  // NVC*NF
#define NHB 8     // NH*NB

// ---------------- scratch (device globals; no allocations allowed) ----------
__device__ __half g_Q[(size_t)NHB * NT * DQK];   // 8 MB
__device__ __half g_K[(size_t)NHB * NT * DQK];   // 8 MB
__device__ __half g_V[(size_t)NHB * NT * DV];    // 32 MB
__device__ __half g_Vt[(size_t)NHB * DV * NT];   // 32 MB  V^T per z: [dv][t]
__device__ __half g_E[(size_t)NHB * NT * NT];    // 64 MB  exp(alpha*S)
__device__ float  g_O[(size_t)NHB * NT * DV];    // 64 MB

// ---------------- helpers ----------------------------------------------------
__device__ __forceinline__ uint32_t smem_u32(const void* p) {
    uint32_t a;
    asm("{ .reg .u64 t; cvta.to.shared.u64 t, %1; cvt.u32.u64 %0, t; }" : "=r"(a) : "l"(p));
    return a;
}
__device__ __forceinline__ void cp_async16(uint32_t dst, const void* src) {
    asm volatile("cp.async.cg.shared.global [%0], [%1], 16;" :: "r"(dst), "l"(src) : "memory");
}
__device__ __forceinline__ void cp_commit() { asm volatile("cp.async.commit_group;" ::: "memory"); }
template <int N> __device__ __forceinline__ void cp_wait() {
    asm volatile("cp.async.wait_group %0;" :: "n"(N) : "memory");
}
__device__ __forceinline__ void mma_f16(float* c, const uint32_t* a, const uint32_t* b) {
    asm volatile(
        "mma.sync.aligned.m16n8k16.row.col.f32.f16.f16.f32 "
        "{%0,%1,%2,%3}, {%4,%5,%6,%7}, {%8,%9}, {%0,%1,%2,%3};"
        : "+f"(c[0]), "+f"(c[1]), "+f"(c[2]), "+f"(c[3])
        : "r"(a[0]), "r"(a[1]), "r"(a[2]), "r"(a[3]), "r"(b[0]), "r"(b[1]));
}
__device__ __forceinline__ void ldmx4(uint32_t& r0, uint32_t& r1, uint32_t& r2, uint32_t& r3,
                                      uint32_t addr) {
    asm volatile("ldmatrix.sync.aligned.m8n8.x4.shared.b16 {%0,%1,%2,%3}, [%4];"
        : "=r"(r0), "=r"(r1), "=r"(r2), "=r"(r3) : "r"(addr));
}
__device__ __forceinline__ float2 h2f2(uint32_t u) {
    return __half22float2(*reinterpret_cast<__half2*>(&u));
}

// common tile geometry (both GEMMs)
#define BM 128
#define BN 256
#define BKH 64                       // k halfs per stage
#define SH 72                        // smem row stride in halfs (144 B)
#define A2_TILE_BYTES (BM * SH * 2)  // 18432
#define B2_TILE_BYTES (BN * SH * 2)  // 36864
#define STAGE_BYTES (A2_TILE_BYTES + B2_TILE_BYTES)  // 55296
#define NSTG 3
#define SMEM_GEMM (NSTG * STAGE_BYTES)

#define ISSUE_F16(it, Kd) do {                                                  \
        int _st = (it) % NSTG;                                                  \
        uint32_t _as = smem_u32(smem) + _st * STAGE_BYTES;                      \
        uint32_t _bs = _as + A2_TILE_BYTES;                                     \
        const __half* _ga = A + (size_t)bm * (Kd) + (size_t)(it) * BKH;         \
        const __half* _gb = B + (size_t)bn * (Kd) + (size_t)(it) * BKH;         \
        _Pragma("unroll")                                                       \
        for (int j = 0; j < 4; j++) {                                           \
            int idx = tid + j * 256;                                            \
            int row = idx >> 3, c8 = idx & 7;                                   \
            cp_async16(_as + (uint32_t)(row * SH * 2 + c8 * 16),                \
                       _ga + (size_t)row * (Kd) + c8 * 8);                      \
        }                                                                       \
        _Pragma("unroll")                                                       \
        for (int j = 0; j < 8; j++) {                                           \
            int idx = tid + j * 256;                                            \
            int row = idx >> 3, c8 = idx & 7;                                   \
            cp_async16(_bs + (uint32_t)(row * SH * 2 + c8 * 16),                \
                       _gb + (size_t)row * (Kd) + c8 * 8);                      \
        }                                                                       \
        cp_commit();                                                            \
    } while (0)

// per-lane ldmatrix base offsets (bytes within a stage's A/B tile)
// A quad mt: rows wm+mt*16+(l&15), matrix col-half (l>>4)*16B
#define A_LDM_OFF(mt) ((uint32_t)((wm + (mt) * 16 + (lane & 15)) * (SH * 2) + (lane >> 4) * 16))
// B quad q (covers nt=2q,2q+1): rows wn+16q+((l&16)?8:0)+(l&7), frag half ((l>>3)&1)*16B
#define B_LDM_OFF(q) ((uint32_t)((wn + (q) * 16 + ((lane & 16) >> 1) + (lane & 7)) * (SH * 2) + ((lane >> 3) & 1) * 16))

// ================= GEMM 1 (fp16): E = fp16(exp(alpha * Q K^T)) ===============
__global__ __launch_bounds__(256, 1) void gemm_qk_exp(
    const __half* __restrict__ A, const __half* __restrict__ B, __half* __restrict__ C,
    float alpha, size_t sA, size_t sB, size_t sC)
{
    extern __shared__ char smem[];
    const int tid = threadIdx.x;
    const int wid = tid >> 5;
    const int lane = tid & 31;
    const int g = lane >> 2;
    const int tc = lane & 3;

    A += (size_t)blockIdx.z * sA;
    B += (size_t)blockIdx.z * sB;
    C += (size_t)blockIdx.z * sC;
    const int bm = blockIdx.y * BM;
    const int bn = blockIdx.x * BN;
    const int wm = (wid & 1) * 64;
    const int wn = (wid >> 1) * 64;

    uint32_t aOff[4], bOff[4];
#pragma unroll
    for (int mt = 0; mt < 4; mt++) aOff[mt] = A_LDM_OFF(mt);
#pragma unroll
    for (int q = 0; q < 4; q++) bOff[q] = B_LDM_OFF(q) + A2_TILE_BYTES;

    float acc[4][8][4];
#pragma unroll
    for (int mt = 0; mt < 4; mt++)
#pragma unroll
        for (int nt = 0; nt < 8; nt++)
#pragma unroll
            for (int i = 0; i < 4; i++) acc[mt][nt][i] = 0.f;

    const int nk = DQK / BKH;   // 4

    ISSUE_F16(0, DQK);
    ISSUE_F16(1, DQK);

    for (int it = 0; it < nk; it++) {
        if (it < nk - 1) cp_wait<1>(); else cp_wait<0>();
        __syncthreads();
        if (it + 2 < nk) ISSUE_F16(it + 2, DQK);

        uint32_t stg = smem_u32(smem) + (it % NSTG) * STAGE_BYTES;

#pragma unroll
        for (int ks = 0; ks < 4; ks++) {
            uint32_t koff = stg + ks * 32;
            uint32_t a[4][4], b[8][2];
#pragma unroll
            for (int mt = 0; mt < 4; mt++)
                ldmx4(a[mt][0], a[mt][1], a[mt][2], a[mt][3], koff + aOff[mt]);
#pragma unroll
            for (int q = 0; q < 4; q++)
                ldmx4(b[2 * q][0], b[2 * q][1], b[2 * q + 1][0], b[2 * q + 1][1],
                      koff + bOff[q]);
#pragma unroll
            for (int mt = 0; mt < 4; mt++)
#pragma unroll
                for (int nt = 0; nt < 8; nt++)
                    mma_f16(acc[mt][nt], a[mt], b[nt]);
        }
    }

    // epilogue: E = fp16(exp(alpha * S))
#pragma unroll
    for (int mt = 0; mt < 4; mt++) {
#pragma unroll
        for (int nt = 0; nt < 8; nt++) {
            int row = bm + wm + mt * 16 + g;
            int col = bn + wn + nt * 8 + 2 * tc;
            __half2 e0 = __float22half2_rn(
                make_float2(__expf(acc[mt][nt][0] * alpha), __expf(acc[mt][nt][1] * alpha)));
            __half2 e1 = __float22half2_rn(
                make_float2(__expf(acc[mt][nt][2] * alpha), __expf(acc[mt][nt][3] * alpha)));
            *(uint32_t*)&C[(size_t)row * NT + col]       = *(uint32_t*)&e0;
            *(uint32_t*)&C[(size_t)(row + 8) * NT + col] = *(uint32_t*)&e1;
        }
    }
}

// ================= GEMM 2 (fp16): O = (E V) / rowsum(E) ======================
__global__ __launch_bounds__(256, 1) void gemm_pv_norm(
    const __half* __restrict__ A, const __half* __restrict__ B,
    float* __restrict__ C, size_t sA, size_t sB, size_t sC)
{
    extern __shared__ char smem[];
    __shared__ float rowinv[BM];
    const int tid = threadIdx.x;
    const int wid = tid >> 5;
    const int lane = tid & 31;
    const int g = lane >> 2;
    const int tc = lane & 3;

    A += (size_t)blockIdx.z * sA;
    B += (size_t)blockIdx.z * sB;
    C += (size_t)blockIdx.z * sC;
    const int bm = blockIdx.y * BM;
    const int bn = blockIdx.x * BN;
    const int wm = (wid & 1) * 64;
    const int wn = (wid >> 1) * 64;

    uint32_t aOff[4], bOff[4];
#pragma unroll
    for (int mt = 0; mt < 4; mt++) aOff[mt] = A_LDM_OFF(mt);
#pragma unroll
    for (int q = 0; q < 4; q++) bOff[q] = B_LDM_OFF(q) + A2_TILE_BYTES;

    float acc[4][8][4];
#pragma unroll
    for (int mt = 0; mt < 4; mt++)
#pragma unroll
        for (int nt = 0; nt < 8; nt++)
#pragma unroll
            for (int i = 0; i < 4; i++) acc[mt][nt][i] = 0.f;

    float rs[4][2];
#pragma unroll
    for (int mt = 0; mt < 4; mt++) { rs[mt][0] = 0.f; rs[mt][1] = 0.f; }

    const int nk = NT / BKH;   // 32

    ISSUE_F16(0, NT);
    ISSUE_F16(1, NT);

    for (int it = 0; it < nk; it++) {
        if (it < nk - 1) cp_wait<1>(); else cp_wait<0>();
        __syncthreads();
        if (it + 2 < nk) ISSUE_F16(it + 2, NT);

        uint32_t stg = smem_u32(smem) + (it % NSTG) * STAGE_BYTES;

#pragma unroll
        for (int ks = 0; ks < 4; ks++) {
            uint32_t koff = stg + ks * 32;
            uint32_t a[4][4], b[8][2];
#pragma unroll
            for (int mt = 0; mt < 4; mt++)
                ldmx4(a[mt][0], a[mt][1], a[mt][2], a[mt][3], koff + aOff[mt]);
            if (wid < 2) {   // wn==0 warps: exact row sums of E
#pragma unroll
                for (int mt = 0; mt < 4; mt++) {
                    float2 f0 = h2f2(a[mt][0]), f2 = h2f2(a[mt][2]);
                    float2 f1 = h2f2(a[mt][1]), f3 = h2f2(a[mt][3]);
                    rs[mt][0] += (f0.x + f0.y) + (f2.x + f2.y);
                    rs[mt][1] += (f1.x + f1.y) + (f3.x + f3.y);
                }
            }
#pragma unroll
            for (int q = 0; q < 4; q++)
                ldmx4(b[2 * q][0], b[2 * q][1], b[2 * q + 1][0], b[2 * q + 1][1],
                      koff + bOff[q]);
#pragma unroll
            for (int mt = 0; mt < 4; mt++)
#pragma unroll
                for (int nt = 0; nt < 8; nt++)
                    mma_f16(acc[mt][nt], a[mt], b[nt]);
        }
    }

    if (wid < 2) {
#pragma unroll
        for (int mt = 0; mt < 4; mt++) {
#pragma unroll
            for (int h2 = 0; h2 < 2; h2++) {
                float s = rs[mt][h2];
                s += __shfl_xor_sync(0xffffffffu, s, 1);
                s += __shfl_xor_sync(0xffffffffu, s, 2);
                if (tc == 0) rowinv[wm + mt * 16 + g + h2 * 8] = 1.f / s;
            }
        }
    }
    __syncthreads();

#pragma unroll
    for (int mt = 0; mt < 4; mt++) {
        float inv0 = rowinv[wm + mt * 16 + g];
        float inv1 = rowinv[wm + mt * 16 + g + 8];
#pragma unroll
        for (int nt = 0; nt < 8; nt++) {
            int row = bm + wm + mt * 16 + g;
            int col = bn + wn + nt * 8 + 2 * tc;
            float2 v0 = make_float2(acc[mt][nt][0] * inv0, acc[mt][nt][1] * inv0);
            float2 v1 = make_float2(acc[mt][nt][2] * inv1, acc[mt][nt][3] * inv1);
            *(float2*)&C[(size_t)row * DV + col] = v0;
            *(float2*)&C[(size_t)(row + 8) * DV + col] = v1;
        }
    }
}

// ---------------- kernel 1: QKV projection + PReLU + per-head LN ------------
__global__ __launch_bounds__(256) void qkv_kernel(
    const float* __restrict__ x,
    const float* __restrict__ Wq, const float* __restrict__ bq, const float* __restrict__ aq,
    const float* __restrict__ gq, const float* __restrict__ betaq,
    const float* __restrict__ Wk, const float* __restrict__ bk, const float* __restrict__ ak,
    const float* __restrict__ gk, const float* __restrict__ betak,
    const float* __restrict__ Wv, const float* __restrict__ bv, const float* __restrict__ av,
    const float* __restrict__ gv, const float* __restrict__ betav)
{
    __shared__ float sWq[NH * NHC * NC];
    __shared__ float sWk[NH * NHC * NC];
    __shared__ float sWv[NH * NVC * NC];

    int tid = threadIdx.y * 64 + threadIdx.x;
    for (int i = tid; i < NH * NHC * NC; i += 256) { sWq[i] = Wq[i]; sWk[i] = Wk[i]; }
    for (int i = tid; i < NH * NVC * NC; i += 256) { sWv[i] = Wv[i]; }
    __syncthreads();

    int f = threadIdx.x;
    int t = blockIdx.x * 4 + threadIdx.y;
    int b = blockIdx.y;

    const float* xp = x + ((size_t)b * NC * NT + t) * NF + f;

    float xr[NC];
#pragma unroll
    for (int c = 0; c < NC; c++) xr[c] = xp[(size_t)c * NT * NF];

    for (int h = 0; h < NH; h++) {
        float q[NHC], k[NHC], v[NVC];
#pragma unroll
        for (int j = 0; j < NHC; j++) { q[j] = 0.f; k[j] = 0.f; }
#pragma unroll
        for (int j = 0; j < NVC; j++) v[j] = 0.f;

#pragma unroll 4
        for (int c0 = 0; c0 < NC; c0 += 4) {
#pragma unroll
            for (int j = 0; j < NHC; j++) {
                float4 w = *(const float4*)&sWq[(h * NHC + j) * NC + c0];
                q[j] += w.x * xr[c0] + w.y * xr[c0 + 1] + w.z * xr[c0 + 2] + w.w * xr[c0 + 3];
            }
#pragma unroll
            for (int j = 0; j < NHC; j++) {
                float4 w = *(const float4*)&sWk[(h * NHC + j) * NC + c0];
                k[j] += w.x * xr[c0] + w.y * xr[c0 + 1] + w.z * xr[c0 + 2] + w.w * xr[c0 + 3];
            }
#pragma unroll
            for (int j = 0; j < NVC; j++) {
                float4 w = *(const float4*)&sWv[(h * NVC + j) * NC + c0];
                v[j] += w.x * xr[c0] + w.y * xr[c0 + 1] + w.z * xr[c0 + 2] + w.w * xr[c0 + 3];
            }
        }
        {
            float a = aq[h], mu = 0.f;
#pragma unroll
            for (int j = 0; j < NHC; j++) {
                float y = q[j] + bq[h * NHC + j];
                y = (y >= 0.f) ? y : a * y; q[j] = y; mu += y;
            }
            mu *= (1.f / NHC);
            float var = 0.f;
#pragma unroll
            for (int j = 0; j < NHC; j++) { float d = q[j] - mu; var += d * d; }
            float r = rsqrtf(var * (1.f / NHC) + EPSV);
#pragma unroll
            for (int j = 0; j < NHC; j++) {
                float o = (q[j] - mu) * r * gq[h * NHC + j] + betaq[h * NHC + j];
                g_Q[((size_t)(h * NB + b) * NT + t) * DQK + j * NF + f] = __float2half_rn(o);
            }
        }
        {
            float a = ak[h], mu = 0.f;
#pragma unroll
            for (int j = 0; j < NHC; j++) {
                float y = k[j] + bk[h * NHC + j];
                y = (y >= 0.f) ? y : a * y; k[j] = y; mu += y;
            }
            mu *= (1.f / NHC);
            float var = 0.f;
#pragma unroll
            for (int j = 0; j < NHC; j++) { float d = k[j] - mu; var += d * d; }
            float r = rsqrtf(var * (1.f / NHC) + EPSV);
#pragma unroll
            for (int j = 0; j < NHC; j++) {
                float o = (k[j] - mu) * r * gk[h * NHC + j] + betak[h * NHC + j];
                g_K[((size_t)(h * NB + b) * NT + t) * DQK + j * NF + f] = __float2half_rn(o);
            }
        }
        {
            float a = av[h], mu = 0.f;
#pragma unroll
            for (int j = 0; j < NVC; j++) {
                float y = v[j] + bv[h * NVC + j];
                y = (y >= 0.f) ? y : a * y; v[j] = y; mu += y;
            }
            mu *= (1.f / NVC);
            float var = 0.f;
#pragma unroll
            for (int j = 0; j < NVC; j++) { float d = v[j] - mu; var += d * d; }
            float r = rsqrtf(var * (1.f / NVC) + EPSV);
#pragma unroll
            for (int j = 0; j < NVC; j++) {
                float o = (v[j] - mu) * r * gv[h * NVC + j] + betav[h * NVC + j];
                g_V[((size_t)(h * NB + b) * NT + t) * DV + j * NF + f] = __float2half_rn(o);
            }
        }
    }
}

// ---------------- transpose V (fp16): [t][dv] -> [dv][t] per z ----------------
__global__ __launch_bounds__(256) void transpose_v()
{
    __shared__ __half tile[32][33];
    int bt = blockIdx.x * 32, bd = blockIdx.y * 32;
    size_t base = (size_t)blockIdx.z * NT * DV;
    int tx = threadIdx.x, ty = threadIdx.y;
#pragma unroll
    for (int j = 0; j < 4; j++)
        tile[ty + j * 8][tx] = g_V[base + (size_t)(bt + ty + j * 8) * DV + bd + tx];
    __syncthreads();
#pragma unroll
    for (int j = 0; j < 4; j++)
        g_Vt[base + (size_t)(bd + ty + j * 8) * NT + bt + tx] = tile[tx][ty + j * 8];
}

// ---------------- output projection + PReLU + LN + residual ------------------
// block = 256 = 4 o-groups (j=tid>>6) x 64 f (tid&63); one block per (t,b).
__global__ __launch_bounds__(256) void out_kernel(
    const float* __restrict__ x,
    const float* __restrict__ Wp, const float* __restrict__ bp, const float* __restrict__ ap,
    const float* __restrict__ gp, const float* __restrict__ betap,
    float* __restrict__ out)
{
    __shared__ float sWt[NC * 68];     // [c][o]
    __shared__ float sOg[NC * 68];     // [c][f]
    __shared__ float sred1[4][64];
    __shared__ float sred2[4][64];

    const int tid = threadIdx.x;
    const int t = blockIdx.x;
    const int b = blockIdx.y;

    // Wp[o][c] -> sWt[c][o]
    for (int i = tid; i < NC * NC; i += 256) {
        int o = i >> 6, c = i & 63;
        sWt[c * 68 + o] = Wp[i];
    }
    // O gather: heads are contiguous 1024-float segments for this (t,b)
#pragma unroll
    for (int h = 0; h < NH; h++) {
        const float4* src = (const float4*)&g_O[((size_t)(h * NB + b) * NT + t) * DV];
        float4 val = src[tid];
        int vc = tid >> 4;
        int f0 = (tid & 15) * 4;
        *(float4*)&sOg[(h * 16 + vc) * 68 + f0] = val;
    }
    __syncthreads();

    const int j = tid >> 6;       // o-group (warp-uniform)
    const int f = tid & 63;       // freq position (consecutive in warp)
    const int o0 = 16 * j;

    float acc[16];
#pragma unroll
    for (int i = 0; i < 16; i++) acc[i] = 0.f;

#pragma unroll 8
    for (int c = 0; c < NC; c++) {
        float og = sOg[c * 68 + f];
        float4 w0 = *(const float4*)&sWt[c * 68 + o0];
        float4 w1 = *(const float4*)&sWt[c * 68 + o0 + 4];
        float4 w2 = *(const float4*)&sWt[c * 68 + o0 + 8];
        float4 w3 = *(const float4*)&sWt[c * 68 + o0 + 12];
        acc[0] += w0.x * og;  acc[1] += w0.y * og;  acc[2] += w0.z * og;  acc[3] += w0.w * og;
        acc[4] += w1.x * og;  acc[5] += w1.y * og;  acc[6] += w1.z * og;  acc[7] += w1.w * og;
        acc[8] += w2.x * og;  acc[9] += w2.y * og;  acc[10] += w2.z * og; acc[11] += w2.w * og;
        acc[12] += w3.x * og; acc[13] += w3.y * og; acc[14] += w3.z * og; acc[15] += w3.w * og;
    }

    float a = ap[0];
    float s1 = 0.f, s2 = 0.f;
#pragma unroll
    for (int i = 0; i < 16; i++) {
        float y = acc[i] + bp[o0 + i];
        y = (y >= 0.f) ? y : a * y;
        acc[i] = y;
        s1 += y; s2 += y * y;
    }
    sred1[j][f] = s1;
    sred2[j][f] = s2;
    __syncthreads();
    s1 = sred1[0][f] + sred1[1][f] + sred1[2][f] + sred1[3][f];
    s2 = sred2[0][f] + sred2[1][f] + sred2[2][f] + sred2[3][f];
    float mu = s1 * (1.f / NC);
    float var = s2 * (1.f / NC) - mu * mu;
    float r = rsqrtf(var + EPSV);

#pragma unroll
    for (int i = 0; i < 16; i++) {
        int o = o0 + i;
        size_t idx = (((size_t)b * NC + o) * NT + t) * NF + f;
        out[idx] = (acc[i] - mu) * r * gp[o] + betap[o] + x[idx];
    }
}

// ---------------- launch ------------------------------------------------------
extern "C" void kernel_launch(void* const* d_in, const int* in_sizes, int n_in,
                              void* d_out, int out_size)
{
    const float* x     = (const float*)d_in[0];
    const float* Wq    = (const float*)d_in[1];
    const float* bq    = (const float*)d_in[2];
    const float* aq    = (const float*)d_in[3];
    const float* gq    = (const float*)d_in[4];
    const float* betaq = (const float*)d_in[5];
    const float* Wk    = (const float*)d_in[6];
    const float* bk    = (const float*)d_in[7];
    const float* ak    = (const float*)d_in[8];
    const float* gk    = (const float*)d_in[9];
    const float* betak = (const float*)d_in[10];
    const float* Wv    = (const float*)d_in[11];
    const float* bv    = (const float*)d_in[12];
    const float* av    = (const float*)d_in[13];
    const float* gv    = (const float*)d_in[14];
    const float* betav = (const float*)d_in[15];
    const float* Wp    = (const float*)d_in[16];
    const float* bp    = (const float*)d_in[17];
    const float* ap    = (const float*)d_in[18];
    const float* gp    = (const float*)d_in[19];
    const float* betap = (const float*)d_in[20];
    float* out = (float*)d_out;

    float* pO;
    __half *pQ, *pK, *pV, *pVt, *pE;
    cudaGetSymbolAddress((void**)&pQ, g_Q);
    cudaGetSymbolAddress((void**)&pK, g_K);
    cudaGetSymbolAddress((void**)&pV, g_V);
    cudaGetSymbolAddress((void**)&pVt, g_Vt);
    cudaGetSymbolAddress((void**)&pE, g_E);
    cudaGetSymbolAddress((void**)&pO, g_O);

    cudaFuncSetAttribute(gemm_qk_exp, cudaFuncAttributeMaxDynamicSharedMemorySize, SMEM_GEMM);
    cudaFuncSetAttribute(gemm_pv_norm, cudaFuncAttributeMaxDynamicSharedMemorySize, SMEM_GEMM);

    // 1) QKV projections (Q,K,V fp16)
    qkv_kernel<<<dim3(NT / 4, NB), dim3(64, 4)>>>(
        x, Wq, bq, aq, gq, betaq, Wk, bk, ak, gk, betak, Wv, bv, av, gv, betav);

    // 2) V transpose (fp16): [t][dv] -> [dv][t]
    transpose_v<<<dim3(NT / 32, DV / 32, NHB), dim3(32, 8)>>>();

    // 3) E = fp16(exp((1/16) Q K^T))   (fp16 mma + ldmatrix)
    gemm_qk_exp<<<dim3(NT / BN, NT / BM, NHB), 256, SMEM_GEMM>>>(
        pQ, pK, pE, 0.0625f,
        (size_t)NT * DQK, (size_t)NT * DQK, (size_t)NT * NT);

    // 4) O = (E V) / rowsum(E)   (fp16 mma + ldmatrix, in-loop row sums)
    gemm_pv_norm<<<dim3(DV / BN, NT / BM, NHB), 256, SMEM_GEMM>>>(
        pE, pVt, pO,
        (size_t)NT * NT, (size_t)DV * NT, (size_t)NT * DV);

    // 5) output projection + LN + residual
    out_kernel<<<dim3(NT, NB), 256>>>(
        x, Wp, bp, ap, gp, betap, out);
}

// round 10
// speedup vs baseline: 1.5047x; 1.0565x over previous
#include <cuda_runtime.h>
#include <cuda_fp16.h>
#include <cstdint>
#include <cstddef>

#define EPSV 1e-5f

// problem dims (fixed)
#define NB 2
#define NC 64
#define NT 2048
#define NF 64
#define NH 4
#define NHC 4
#define NVC 16
#define DQK 256   // NHC*NF
#define DV  1024  // NVC*NF
#define NHB 8     // NH*NB

// ---------------- scratch (device globals; no allocations allowed) ----------
__device__ __half g_Q[(size_t)NHB * NT * DQK];   // 8 MB
__device__ __half g_K[(size_t)NHB * NT * DQK];   // 8 MB
__device__ __half g_V[(size_t)NHB * NT * DV];    // 32 MB
__device__ __half g_Vt[(size_t)NHB * DV * NT];   // 32 MB  V^T per z: [dv][t]
__device__ __half g_E[(size_t)NHB * NT * NT];    // 64 MB  exp(alpha*S)
__device__ float  g_O[(size_t)NHB * NT * DV];    // 64 MB

// ---------------- helpers ----------------------------------------------------
__device__ __forceinline__ uint32_t smem_u32(const void* p) {
    uint32_t a;
    asm("{ .reg .u64 t; cvta.to.shared.u64 t, %1; cvt.u32.u64 %0, t; }" : "=r"(a) : "l"(p));
    return a;
}
__device__ __forceinline__ void cp_async16(uint32_t dst, const void* src) {
    asm volatile("cp.async.cg.shared.global [%0], [%1], 16;" :: "r"(dst), "l"(src) : "memory");
}
__device__ __forceinline__ void cp_commit() { asm volatile("cp.async.commit_group;" ::: "memory"); }
template <int N> __device__ __forceinline__ void cp_wait() {
    asm volatile("cp.async.wait_group %0;" :: "n"(N) : "memory");
}
__device__ __forceinline__ void mma_f16(float* c, const uint32_t* a, const uint32_t* b) {
    asm volatile(
        "mma.sync.aligned.m16n8k16.row.col.f32.f16.f16.f32 "
        "{%0,%1,%2,%3}, {%4,%5,%6,%7}, {%8,%9}, {%0,%1,%2,%3};"
        : "+f"(c[0]), "+f"(c[1]), "+f"(c[2]), "+f"(c[3])
        : "r"(a[0]), "r"(a[1]), "r"(a[2]), "r"(a[3]), "r"(b[0]), "r"(b[1]));
}
__device__ __forceinline__ void ldmx4(uint32_t& r0, uint32_t& r1, uint32_t& r2, uint32_t& r3,
                                      uint32_t addr) {
    asm volatile("ldmatrix.sync.aligned.m8n8.x4.shared.b16 {%0,%1,%2,%3}, [%4];"
        : "=r"(r0), "=r"(r1), "=r"(r2), "=r"(r3) : "r"(addr));
}
__device__ __forceinline__ float2 h2f2(uint32_t u) {
    return __half22float2(*reinterpret_cast<__half2*>(&u));
}

// common tile geometry (both GEMMs): 128x128 tile, 2 CTAs/SM
#define BM 128
#define BN 128
#define BKH 64                       // k halfs per stage
#define SH 72                        // smem row stride in halfs (144 B)
#define A2_TILE_BYTES (BM * SH * 2)  // 18432
#define B2_TILE_BYTES (BN * SH * 2)  // 18432
#define STAGE_BYTES (A2_TILE_BYTES + B2_TILE_BYTES)  // 36864
#define NSTG 3
#define SMEM_GEMM (NSTG * STAGE_BYTES)               // 110592

#define ISSUE_F16(it, Kd) do {                                                  \
        int _st = (it) % NSTG;                                                  \
        uint32_t _as = smem_u32(smem) + _st * STAGE_BYTES;                      \
        uint32_t _bs = _as + A2_TILE_BYTES;                                     \
        const __half* _ga = A + (size_t)bm * (Kd) + (size_t)(it) * BKH;         \
        const __half* _gb = B + (size_t)bn * (Kd) + (size_t)(it) * BKH;         \
        _Pragma("unroll")                                                       \
        for (int j = 0; j < 4; j++) {                                           \
            int idx = tid + j * 256;                                            \
            int row = idx >> 3, c8 = idx & 7;                                   \
            cp_async16(_as + (uint32_t)(row * SH * 2 + c8 * 16),                \
                       _ga + (size_t)row * (Kd) + c8 * 8);                      \
        }                                                                       \
        _Pragma("unroll")                                                       \
        for (int j = 0; j < 4; j++) {                                           \
            int idx = tid + j * 256;                                            \
            int row = idx >> 3, c8 = idx & 7;                                   \
            cp_async16(_bs + (uint32_t)(row * SH * 2 + c8 * 16),                \
                       _gb + (size_t)row * (Kd) + c8 * 8);                      \
        }                                                                       \
        cp_commit();                                                            \
    } while (0)

// per-lane ldmatrix base offsets (bytes within a stage's A/B tile)
#define A_LDM_OFF(mt) ((uint32_t)((wm + (mt) * 16 + (lane & 15)) * (SH * 2) + (lane >> 4) * 16))
#define B_LDM_OFF(q) ((uint32_t)((wn + (q) * 16 + ((lane & 16) >> 1) + (lane & 7)) * (SH * 2) + ((lane >> 3) & 1) * 16))

// ================= GEMM 1 (fp16): E = fp16(exp(alpha * Q K^T)) ===============
__global__ __launch_bounds__(256, 2) void gemm_qk_exp(
    const __half* __restrict__ A, const __half* __restrict__ B, __half* __restrict__ C,
    float alpha, size_t sA, size_t sB, size_t sC)
{
    extern __shared__ char smem[];
    const int tid = threadIdx.x;
    const int wid = tid >> 5;
    const int lane = tid & 31;
    const int g = lane >> 2;
    const int tc = lane & 3;

    A += (size_t)blockIdx.z * sA;
    B += (size_t)blockIdx.z * sB;
    C += (size_t)blockIdx.z * sC;
    const int bm = blockIdx.y * BM;
    const int bn = blockIdx.x * BN;
    const int wm = (wid & 1) * 64;
    const int wn = (wid >> 1) * 32;

    uint32_t aOff[4], bOff[2];
#pragma unroll
    for (int mt = 0; mt < 4; mt++) aOff[mt] = A_LDM_OFF(mt);
#pragma unroll
    for (int q = 0; q < 2; q++) bOff[q] = B_LDM_OFF(q) + A2_TILE_BYTES;

    float acc[4][4][4];
#pragma unroll
    for (int mt = 0; mt < 4; mt++)
#pragma unroll
        for (int nt = 0; nt < 4; nt++)
#pragma unroll
            for (int i = 0; i < 4; i++) acc[mt][nt][i] = 0.f;

    const int nk = DQK / BKH;   // 4

    ISSUE_F16(0, DQK);
    ISSUE_F16(1, DQK);

    for (int it = 0; it < nk; it++) {
        if (it < nk - 1) cp_wait<1>(); else cp_wait<0>();
        __syncthreads();
        if (it + 2 < nk) ISSUE_F16(it + 2, DQK);

        uint32_t stg = smem_u32(smem) + (it % NSTG) * STAGE_BYTES;

#pragma unroll
        for (int ks = 0; ks < 4; ks++) {
            uint32_t koff = stg + ks * 32;
            uint32_t a[4][4], b[4][2];
#pragma unroll
            for (int mt = 0; mt < 4; mt++)
                ldmx4(a[mt][0], a[mt][1], a[mt][2], a[mt][3], koff + aOff[mt]);
#pragma unroll
            for (int q = 0; q < 2; q++)
                ldmx4(b[2 * q][0], b[2 * q][1], b[2 * q + 1][0], b[2 * q + 1][1],
                      koff + bOff[q]);
#pragma unroll
            for (int mt = 0; mt < 4; mt++)
#pragma unroll
                for (int nt = 0; nt < 4; nt++)
                    mma_f16(acc[mt][nt], a[mt], b[nt]);
        }
    }

    // epilogue: E = fp16(exp(alpha * S))
#pragma unroll
    for (int mt = 0; mt < 4; mt++) {
#pragma unroll
        for (int nt = 0; nt < 4; nt++) {
            int row = bm + wm + mt * 16 + g;
            int col = bn + wn + nt * 8 + 2 * tc;
            __half2 e0 = __float22half2_rn(
                make_float2(__expf(acc[mt][nt][0] * alpha), __expf(acc[mt][nt][1] * alpha)));
            __half2 e1 = __float22half2_rn(
                make_float2(__expf(acc[mt][nt][2] * alpha), __expf(acc[mt][nt][3] * alpha)));
            *(uint32_t*)&C[(size_t)row * NT + col]       = *(uint32_t*)&e0;
            *(uint32_t*)&C[(size_t)(row + 8) * NT + col] = *(uint32_t*)&e1;
        }
    }
}

// ================= GEMM 2 (fp16): O = (E V) / rowsum(E) ======================
__global__ __launch_bounds__(256, 2) void gemm_pv_norm(
    const __half* __restrict__ A, const __half* __restrict__ B,
    float* __restrict__ C, size_t sA, size_t sB, size_t sC)
{
    extern __shared__ char smem[];
    __shared__ float rowinv[BM];
    const int tid = threadIdx.x;
    const int wid = tid >> 5;
    const int lane = tid & 31;
    const int g = lane >> 2;
    const int tc = lane & 3;

    A += (size_t)blockIdx.z * sA;
    B += (size_t)blockIdx.z * sB;
    C += (size_t)blockIdx.z * sC;
    const int bm = blockIdx.y * BM;
    const int bn = blockIdx.x * BN;
    const int wm = (wid & 1) * 64;
    const int wn = (wid >> 1) * 32;

    uint32_t aOff[4], bOff[2];
#pragma unroll
    for (int mt = 0; mt < 4; mt++) aOff[mt] = A_LDM_OFF(mt);
#pragma unroll
    for (int q = 0; q < 2; q++) bOff[q] = B_LDM_OFF(q) + A2_TILE_BYTES;

    float acc[4][4][4];
#pragma unroll
    for (int mt = 0; mt < 4; mt++)
#pragma unroll
        for (int nt = 0; nt < 4; nt++)
#pragma unroll
            for (int i = 0; i < 4; i++) acc[mt][nt][i] = 0.f;

    float rs[4][2];
#pragma unroll
    for (int mt = 0; mt < 4; mt++) { rs[mt][0] = 0.f; rs[mt][1] = 0.f; }

    const int nk = NT / BKH;   // 32

    ISSUE_F16(0, NT);
    ISSUE_F16(1, NT);

    for (int it = 0; it < nk; it++) {
        if (it < nk - 1) cp_wait<1>(); else cp_wait<0>();
        __syncthreads();
        if (it + 2 < nk) ISSUE_F16(it + 2, NT);

        uint32_t stg = smem_u32(smem) + (it % NSTG) * STAGE_BYTES;

#pragma unroll
        for (int ks = 0; ks < 4; ks++) {
            uint32_t koff = stg + ks * 32;
            uint32_t a[4][4], b[4][2];
#pragma unroll
            for (int mt = 0; mt < 4; mt++)
                ldmx4(a[mt][0], a[mt][1], a[mt][2], a[mt][3], koff + aOff[mt]);
            if (wid < 2) {   // wn==0 warps: exact row sums of E
#pragma unroll
                for (int mt = 0; mt < 4; mt++) {
                    float2 f0 = h2f2(a[mt][0]), f2 = h2f2(a[mt][2]);
                    float2 f1 = h2f2(a[mt][1]), f3 = h2f2(a[mt][3]);
                    rs[mt][0] += (f0.x + f0.y) + (f2.x + f2.y);
                    rs[mt][1] += (f1.x + f1.y) + (f3.x + f3.y);
                }
            }
#pragma unroll
            for (int q = 0; q < 2; q++)
                ldmx4(b[2 * q][0], b[2 * q][1], b[2 * q + 1][0], b[2 * q + 1][1],
                      koff + bOff[q]);
#pragma unroll
            for (int mt = 0; mt < 4; mt++)
#pragma unroll
                for (int nt = 0; nt < 4; nt++)
                    mma_f16(acc[mt][nt], a[mt], b[nt]);
        }
    }

    if (wid < 2) {
#pragma unroll
        for (int mt = 0; mt < 4; mt++) {
#pragma unroll
            for (int h2 = 0; h2 < 2; h2++) {
                float s = rs[mt][h2];
                s += __shfl_xor_sync(0xffffffffu, s, 1);
                s += __shfl_xor_sync(0xffffffffu, s, 2);
                if (tc == 0) rowinv[wm + mt * 16 + g + h2 * 8] = 1.f / s;
            }
        }
    }
    __syncthreads();

#pragma unroll
    for (int mt = 0; mt < 4; mt++) {
        float inv0 = rowinv[wm + mt * 16 + g];
        float inv1 = rowinv[wm + mt * 16 + g + 8];
#pragma unroll
        for (int nt = 0; nt < 4; nt++) {
            int row = bm + wm + mt * 16 + g;
            int col = bn + wn + nt * 8 + 2 * tc;
            float2 v0 = make_float2(acc[mt][nt][0] * inv0, acc[mt][nt][1] * inv0);
            float2 v1 = make_float2(acc[mt][nt][2] * inv1, acc[mt][nt][3] * inv1);
            *(float2*)&C[(size_t)row * DV + col] = v0;
            *(float2*)&C[(size_t)(row + 8) * DV + col] = v1;
        }
    }
}

// ---------------- kernel 1: QKV projection + PReLU + per-head LN ------------
__global__ __launch_bounds__(256) void qkv_kernel(
    const float* __restrict__ x,
    const float* __restrict__ Wq, const float* __restrict__ bq, const float* __restrict__ aq,
    const float* __restrict__ gq, const float* __restrict__ betaq,
    const float* __restrict__ Wk, const float* __restrict__ bk, const float* __restrict__ ak,
    const float* __restrict__ gk, const float* __restrict__ betak,
    const float* __restrict__ Wv, const float* __restrict__ bv, const float* __restrict__ av,
    const float* __restrict__ gv, const float* __restrict__ betav)
{
    __shared__ float sWq[NH * NHC * NC];
    __shared__ float sWk[NH * NHC * NC];
    __shared__ float sWv[NH * NVC * NC];

    int tid = threadIdx.y * 64 + threadIdx.x;
    for (int i = tid; i < NH * NHC * NC; i += 256) { sWq[i] = Wq[i]; sWk[i] = Wk[i]; }
    for (int i = tid; i < NH * NVC * NC; i += 256) { sWv[i] = Wv[i]; }
    __syncthreads();

    int f = threadIdx.x;
    int t = blockIdx.x * 4 + threadIdx.y;
    int b = blockIdx.y;

    const float* xp = x + ((size_t)b * NC * NT + t) * NF + f;

    float xr[NC];
#pragma unroll
    for (int c = 0; c < NC; c++) xr[c] = xp[(size_t)c * NT * NF];

    for (int h = 0; h < NH; h++) {
        float q[NHC], k[NHC], v[NVC];
#pragma unroll
        for (int j = 0; j < NHC; j++) { q[j] = 0.f; k[j] = 0.f; }
#pragma unroll
        for (int j = 0; j < NVC; j++) v[j] = 0.f;

#pragma unroll 4
        for (int c0 = 0; c0 < NC; c0 += 4) {
#pragma unroll
            for (int j = 0; j < NHC; j++) {
                float4 w = *(const float4*)&sWq[(h * NHC + j) * NC + c0];
                q[j] += w.x * xr[c0] + w.y * xr[c0 + 1] + w.z * xr[c0 + 2] + w.w * xr[c0 + 3];
            }
#pragma unroll
            for (int j = 0; j < NHC; j++) {
                float4 w = *(const float4*)&sWk[(h * NHC + j) * NC + c0];
                k[j] += w.x * xr[c0] + w.y * xr[c0 + 1] + w.z * xr[c0 + 2] + w.w * xr[c0 + 3];
            }
#pragma unroll
            for (int j = 0; j < NVC; j++) {
                float4 w = *(const float4*)&sWv[(h * NVC + j) * NC + c0];
                v[j] += w.x * xr[c0] + w.y * xr[c0 + 1] + w.z * xr[c0 + 2] + w.w * xr[c0 + 3];
            }
        }
        {
            float a = aq[h], mu = 0.f;
#pragma unroll
            for (int j = 0; j < NHC; j++) {
                float y = q[j] + bq[h * NHC + j];
                y = (y >= 0.f) ? y : a * y; q[j] = y; mu += y;
            }
            mu *= (1.f / NHC);
            float var = 0.f;
#pragma unroll
            for (int j = 0; j < NHC; j++) { float d = q[j] - mu; var += d * d; }
            float r = rsqrtf(var * (1.f / NHC) + EPSV);
#pragma unroll
            for (int j = 0; j < NHC; j++) {
                float o = (q[j] - mu) * r * gq[h * NHC + j] + betaq[h * NHC + j];
                g_Q[((size_t)(h * NB + b) * NT + t) * DQK + j * NF + f] = __float2half_rn(o);
            }
        }
        {
            float a = ak[h], mu = 0.f;
#pragma unroll
            for (int j = 0; j < NHC; j++) {
                float y = k[j] + bk[h * NHC + j];
                y = (y >= 0.f) ? y : a * y; k[j] = y; mu += y;
            }
            mu *= (1.f / NHC);
            float var = 0.f;
#pragma unroll
            for (int j = 0; j < NHC; j++) { float d = k[j] - mu; var += d * d; }
            float r = rsqrtf(var * (1.f / NHC) + EPSV);
#pragma unroll
            for (int j = 0; j < NHC; j++) {
                float o = (k[j] - mu) * r * gk[h * NHC + j] + betak[h * NHC + j];
                g_K[((size_t)(h * NB + b) * NT + t) * DQK + j * NF + f] = __float2half_rn(o);
            }
        }
        {
            float a = av[h], mu = 0.f;
#pragma unroll
            for (int j = 0; j < NVC; j++) {
                float y = v[j] + bv[h * NVC + j];
                y = (y >= 0.f) ? y : a * y; v[j] = y; mu += y;
            }
            mu *= (1.f / NVC);
            float var = 0.f;
#pragma unroll
            for (int j = 0; j < NVC; j++) { float d = v[j] - mu; var += d * d; }
            float r = rsqrtf(var * (1.f / NVC) + EPSV);
#pragma unroll
            for (int j = 0; j < NVC; j++) {
                float o = (v[j] - mu) * r * gv[h * NVC + j] + betav[h * NVC + j];
                g_V[((size_t)(h * NB + b) * NT + t) * DV + j * NF + f] = __float2half_rn(o);
            }
        }
    }
}

// ---------------- transpose V (fp16): [t][dv] -> [dv][t] per z ----------------
__global__ __launch_bounds__(256) void transpose_v()
{
    __shared__ __half tile[32][33];
    int bt = blockIdx.x * 32, bd = blockIdx.y * 32;
    size_t base = (size_t)blockIdx.z * NT * DV;
    int tx = threadIdx.x, ty = threadIdx.y;
#pragma unroll
    for (int j = 0; j < 4; j++)
        tile[ty + j * 8][tx] = g_V[base + (size_t)(bt + ty + j * 8) * DV + bd + tx];
    __syncthreads();
#pragma unroll
    for (int j = 0; j < 4; j++)
        g_Vt[base + (size_t)(bd + ty + j * 8) * NT + bt + tx] = tile[tx][ty + j * 8];
}

// ---------------- output projection + PReLU + LN + residual ------------------
// block = 256 = 4 o-groups (j=tid>>6) x 64 f (tid&63); one block per (t,b).
__global__ __launch_bounds__(256) void out_kernel(
    const float* __restrict__ x,
    const float* __restrict__ Wp, const float* __restrict__ bp, const float* __restrict__ ap,
    const float* __restrict__ gp, const float* __restrict__ betap,
    float* __restrict__ out)
{
    __shared__ float sWt[NC * 68];     // [c][o]
    __shared__ float sOg[NC * 68];     // [c][f]
    __shared__ float sred1[4][64];
    __shared__ float sred2[4][64];

    const int tid = threadIdx.x;
    const int t = blockIdx.x;
    const int b = blockIdx.y;

    // Wp[o][c] -> sWt[c][o]
    for (int i = tid; i < NC * NC; i += 256) {
        int o = i >> 6, c = i & 63;
        sWt[c * 68 + o] = Wp[i];
    }
    // O gather: heads are contiguous 1024-float segments for this (t,b)
#pragma unroll
    for (int h = 0; h < NH; h++) {
        const float4* src = (const float4*)&g_O[((size_t)(h * NB + b) * NT + t) * DV];
        float4 val = src[tid];
        int vc = tid >> 4;
        int f0 = (tid & 15) * 4;
        *(float4*)&sOg[(h * 16 + vc) * 68 + f0] = val;
    }
    __syncthreads();

    const int j = tid >> 6;       // o-group (warp-uniform)
    const int f = tid & 63;       // freq position (consecutive in warp)
    const int o0 = 16 * j;

    float acc[16];
#pragma unroll
    for (int i = 0; i < 16; i++) acc[i] = 0.f;

#pragma unroll 8
    for (int c = 0; c < NC; c++) {
        float og = sOg[c * 68 + f];
        float4 w0 = *(const float4*)&sWt[c * 68 + o0];
        float4 w1 = *(const float4*)&sWt[c * 68 + o0 + 4];
        float4 w2 = *(const float4*)&sWt[c * 68 + o0 + 8];
        float4 w3 = *(const float4*)&sWt[c * 68 + o0 + 12];
        acc[0] += w0.x * og;  acc[1] += w0.y * og;  acc[2] += w0.z * og;  acc[3] += w0.w * og;
        acc[4] += w1.x * og;  acc[5] += w1.y * og;  acc[6] += w1.z * og;  acc[7] += w1.w * og;
        acc[8] += w2.x * og;  acc[9] += w2.y * og;  acc[10] += w2.z * og; acc[11] += w2.w * og;
        acc[12] += w3.x * og; acc[13] += w3.y * og; acc[14] += w3.z * og; acc[15] += w3.w * og;
    }

    float a = ap[0];
    float s1 = 0.f, s2 = 0.f;
#pragma unroll
    for (int i = 0; i < 16; i++) {
        float y = acc[i] + bp[o0 + i];
        y = (y >= 0.f) ? y : a * y;
        acc[i] = y;
        s1 += y; s2 += y * y;
    }
    sred1[j][f] = s1;
    sred2[j][f] = s2;
    __syncthreads();
    s1 = sred1[0][f] + sred1[1][f] + sred1[2][f] + sred1[3][f];
    s2 = sred2[0][f] + sred2[1][f] + sred2[2][f] + sred2[3][f];
    float mu = s1 * (1.f / NC);
    float var = s2 * (1.f / NC) - mu * mu;
    float r = rsqrtf(var + EPSV);

#pragma unroll
    for (int i = 0; i < 16; i++) {
        int o = o0 + i;
        size_t idx = (((size_t)b * NC + o) * NT + t) * NF + f;
        out[idx] = (acc[i] - mu) * r * gp[o] + betap[o] + x[idx];
    }
}

// ---------------- launch ------------------------------------------------------
extern "C" void kernel_launch(void* const* d_in, const int* in_sizes, int n_in,
                              void* d_out, int out_size)
{
    const float* x     = (const float*)d_in[0];
    const float* Wq    = (const float*)d_in[1];
    const float* bq    = (const float*)d_in[2];
    const float* aq    = (const float*)d_in[3];
    const float* gq    = (const float*)d_in[4];
    const float* betaq = (const float*)d_in[5];
    const float* Wk    = (const float*)d_in[6];
    const float* bk    = (const float*)d_in[7];
    const float* ak    = (const float*)d_in[8];
    const float* gk    = (const float*)d_in[9];
    const float* betak = (const float*)d_in[10];
    const float* Wv    = (const float*)d_in[11];
    const float* bv    = (const float*)d_in[12];
    const float* av    = (const float*)d_in[13];
    const float* gv    = (const float*)d_in[14];
    const float* betav = (const float*)d_in[15];
    const float* Wp    = (const float*)d_in[16];
    const float* bp    = (const float*)d_in[17];
    const float* ap    = (const float*)d_in[18];
    const float* gp    = (const float*)d_in[19];
    const float* betap = (const float*)d_in[20];
    float* out = (float*)d_out;

    float* pO;
    __half *pQ, *pK, *pV, *pVt, *pE;
    cudaGetSymbolAddress((void**)&pQ, g_Q);
    cudaGetSymbolAddress((void**)&pK, g_K);
    cudaGetSymbolAddress((void**)&pV, g_V);
    cudaGetSymbolAddress((void**)&pVt, g_Vt);
    cudaGetSymbolAddress((void**)&pE, g_E);
    cudaGetSymbolAddress((void**)&pO, g_O);

    cudaFuncSetAttribute(gemm_qk_exp, cudaFuncAttributeMaxDynamicSharedMemorySize, SMEM_GEMM);
    cudaFuncSetAttribute(gemm_pv_norm, cudaFuncAttributeMaxDynamicSharedMemorySize, SMEM_GEMM);

    // 1) QKV projections (Q,K,V fp16)
    qkv_kernel<<<dim3(NT / 4, NB), dim3(64, 4)>>>(
        x, Wq, bq, aq, gq, betaq, Wk, bk, ak, gk, betak, Wv, bv, av, gv, betav);

    // 2) V transpose (fp16): [t][dv] -> [dv][t]
    transpose_v<<<dim3(NT / 32, DV / 32, NHB), dim3(32, 8)>>>();

    // 3) E = fp16(exp((1/16) Q K^T))   (fp16 mma + ldmatrix, 2 CTA/SM)
    gemm_qk_exp<<<dim3(NT / BN, NT / BM, NHB), 256, SMEM_GEMM>>>(
        pQ, pK, pE, 0.0625f,
        (size_t)NT * DQK, (size_t)NT * DQK, (size_t)NT * NT);

    // 4) O = (E V) / rowsum(E)   (fp16 mma + ldmatrix, 2 CTA/SM)
    gemm_pv_norm<<<dim3(DV / BN, NT / BM, NHB), 256, SMEM_GEMM>>>(
        pE, pVt, pO,
        (size_t)NT * NT, (size_t)DV * NT, (size_t)NT * DV);

    // 5) output projection + LN + residual
    out_kernel<<<dim3(NT, NB), 256>>>(
        x, Wp, bp, ap, gp, betap, out);
}

// round 12
// speedup vs baseline: 1.5962x; 1.0608x over previous
#include <cuda_runtime.h>
#include <cuda_fp16.h>
#include <cstdint>
#include <cstddef>

#define EPSV 1e-5f

// problem dims (fixed)
#define NB 2
#define NC 64
#define NT 2048
#define NF 64
#define NH 4
#define NHC 4
#define NVC 16
#define DQK 256   // NHC*NF
#define DV  1024  // NVC*NF
#define NHB 8     // NH*NB
#define NTF 131072  // NT*NF per (b,c)

// ---------------- scratch (device globals; no allocations allowed) ----------
__device__ __half g_xh[(size_t)NB * NC * NTF];   // 34 MB  x in fp16
__device__ __half g_Q[(size_t)NHB * NT * DQK];   // 8 MB
__device__ __half g_K[(size_t)NHB * NT * DQK];   // 8 MB
__device__ __half g_V[(size_t)NHB * NT * DV];    // 32 MB
__device__ __half g_Vt[(size_t)NHB * DV * NT];   // 32 MB  V^T per z: [dv][t]
__device__ __half g_E[(size_t)NHB * NT * NT];    // 64 MB  exp(alpha*S)
__device__ float  g_O[(size_t)NHB * NT * DV];    // 64 MB

// ---------------- helpers ----------------------------------------------------
__device__ __forceinline__ uint32_t smem_u32(const void* p) {
    uint32_t a;
    asm("{ .reg .u64 t; cvta.to.shared.u64 t, %1; cvt.u32.u64 %0, t; }" : "=r"(a) : "l"(p));
    return a;
}
__device__ __forceinline__ void cp_async16(uint32_t dst, const void* src) {
    asm volatile("cp.async.cg.shared.global [%0], [%1], 16;" :: "r"(dst), "l"(src) : "memory");
}
__device__ __forceinline__ void cp_commit() { asm volatile("cp.async.commit_group;" ::: "memory"); }
template <int N> __device__ __forceinline__ void cp_wait() {
    asm volatile("cp.async.wait_group %0;" :: "n"(N) : "memory");
}
__device__ __forceinline__ void mma_f16(float* c, const uint32_t* a, const uint32_t* b) {
    asm volatile(
        "mma.sync.aligned.m16n8k16.row.col.f32.f16.f16.f32 "
        "{%0,%1,%2,%3}, {%4,%5,%6,%7}, {%8,%9}, {%0,%1,%2,%3};"
        : "+f"(c[0]), "+f"(c[1]), "+f"(c[2]), "+f"(c[3])
        : "r"(a[0]), "r"(a[1]), "r"(a[2]), "r"(a[3]), "r"(b[0]), "r"(b[1]));
}
__device__ __forceinline__ void ldmx4(uint32_t& r0, uint32_t& r1, uint32_t& r2, uint32_t& r3,
                                      uint32_t addr) {
    asm volatile("ldmatrix.sync.aligned.m8n8.x4.shared.b16 {%0,%1,%2,%3}, [%4];"
        : "=r"(r0), "=r"(r1), "=r"(r2), "=r"(r3) : "r"(addr));
}
__device__ __forceinline__ float2 h2f2(uint32_t u) {
    return __half22float2(*reinterpret_cast<__half2*>(&u));
}

// common GEMM tile geometry: 128x128 tile, 2 CTAs/SM
#define BM 128
#define BN 128
#define BKH 64                       // k halfs per stage
#define SH 72                        // smem row stride in halfs (144 B)
#define A2_TILE_BYTES (BM * SH * 2)  // 18432
#define B2_TILE_BYTES (BN * SH * 2)  // 18432
#define STAGE_BYTES (A2_TILE_BYTES + B2_TILE_BYTES)  // 36864
#define NSTG 3
#define SMEM_GEMM (NSTG * STAGE_BYTES)               // 110592

#define ISSUE_F16(it, Kd) do {                                                  \
        int _st = (it) % NSTG;                                                  \
        uint32_t _as = smem_u32(smem) + _st * STAGE_BYTES;                      \
        uint32_t _bs = _as + A2_TILE_BYTES;                                     \
        const __half* _ga = A + (size_t)bm * (Kd) + (size_t)(it) * BKH;         \
        const __half* _gb = B + (size_t)bn * (Kd) + (size_t)(it) * BKH;         \
        _Pragma("unroll")                                                       \
        for (int j = 0; j < 4; j++) {                                           \
            int idx = tid + j * 256;                                            \
            int row = idx >> 3, c8 = idx & 7;                                   \
            cp_async16(_as + (uint32_t)(row * SH * 2 + c8 * 16),                \
                       _ga + (size_t)row * (Kd) + c8 * 8);                      \
        }                                                                       \
        _Pragma("unroll")                                                       \
        for (int j = 0; j < 4; j++) {                                           \
            int idx = tid + j * 256;                                            \
            int row = idx >> 3, c8 = idx & 7;                                   \
            cp_async16(_bs + (uint32_t)(row * SH * 2 + c8 * 16),                \
                       _gb + (size_t)row * (Kd) + c8 * 8);                      \
        }                                                                       \
        cp_commit();                                                            \
    } while (0)

// per-lane ldmatrix base offsets (bytes; stride SH halfs)
#define A_LDM_OFF(base_row) ((uint32_t)(((base_row) + (lane & 15)) * (SH * 2) + (lane >> 4) * 16))
#define B_LDM_OFF(base_row) ((uint32_t)(((base_row) + ((lane & 16) >> 1) + (lane & 7)) * (SH * 2) + ((lane >> 3) & 1) * 16))

// ldmatrix offset macros for qkv_tc (stride QSH halfs)
#define QSH 72
#define A_LDM_OFF_Q(base_row) ((uint32_t)(((base_row) + (lane & 15)) * (QSH * 2) + (lane >> 4) * 16))
#define B_LDM_OFF_Q(base_row) ((uint32_t)(((base_row) + ((lane & 16) >> 1) + (lane & 7)) * (QSH * 2) + ((lane >> 3) & 1) * 16))

// ================= GEMM 1 (fp16): E = fp16(exp(alpha * Q K^T)) ===============
__global__ __launch_bounds__(256, 2) void gemm_qk_exp(
    const __half* __restrict__ A, const __half* __restrict__ B, __half* __restrict__ C,
    float alpha, size_t sA, size_t sB, size_t sC)
{
    extern __shared__ char smem[];
    const int tid = threadIdx.x;
    const int wid = tid >> 5;
    const int lane = tid & 31;
    const int g = lane >> 2;
    const int tc = lane & 3;

    A += (size_t)blockIdx.z * sA;
    B += (size_t)blockIdx.z * sB;
    C += (size_t)blockIdx.z * sC;
    const int bm = blockIdx.y * BM;
    const int bn = blockIdx.x * BN;
    const int wm = (wid & 1) * 64;
    const int wn = (wid >> 1) * 32;

    uint32_t aOff[4], bOff[2];
#pragma unroll
    for (int mt = 0; mt < 4; mt++) aOff[mt] = A_LDM_OFF(wm + mt * 16);
#pragma unroll
    for (int q = 0; q < 2; q++) bOff[q] = B_LDM_OFF(wn + q * 16) + A2_TILE_BYTES;

    float acc[4][4][4];
#pragma unroll
    for (int mt = 0; mt < 4; mt++)
#pragma unroll
        for (int nt = 0; nt < 4; nt++)
#pragma unroll
            for (int i = 0; i < 4; i++) acc[mt][nt][i] = 0.f;

    const int nk = DQK / BKH;   // 4

    ISSUE_F16(0, DQK);
    ISSUE_F16(1, DQK);

    for (int it = 0; it < nk; it++) {
        if (it < nk - 1) cp_wait<1>(); else cp_wait<0>();
        __syncthreads();
        if (it + 2 < nk) ISSUE_F16(it + 2, DQK);

        uint32_t stg = smem_u32(smem) + (it % NSTG) * STAGE_BYTES;

#pragma unroll
        for (int ks = 0; ks < 4; ks++) {
            uint32_t koff = stg + ks * 32;
            uint32_t a[4][4], b[4][2];
#pragma unroll
            for (int mt = 0; mt < 4; mt++)
                ldmx4(a[mt][0], a[mt][1], a[mt][2], a[mt][3], koff + aOff[mt]);
#pragma unroll
            for (int q = 0; q < 2; q++)
                ldmx4(b[2 * q][0], b[2 * q][1], b[2 * q + 1][0], b[2 * q + 1][1],
                      koff + bOff[q]);
#pragma unroll
            for (int mt = 0; mt < 4; mt++)
#pragma unroll
                for (int nt = 0; nt < 4; nt++)
                    mma_f16(acc[mt][nt], a[mt], b[nt]);
        }
    }

    // epilogue: E = fp16(exp(alpha * S))
#pragma unroll
    for (int mt = 0; mt < 4; mt++) {
#pragma unroll
        for (int nt = 0; nt < 4; nt++) {
            int row = bm + wm + mt * 16 + g;
            int col = bn + wn + nt * 8 + 2 * tc;
            __half2 e0 = __float22half2_rn(
                make_float2(__expf(acc[mt][nt][0] * alpha), __expf(acc[mt][nt][1] * alpha)));
            __half2 e1 = __float22half2_rn(
                make_float2(__expf(acc[mt][nt][2] * alpha), __expf(acc[mt][nt][3] * alpha)));
            *(uint32_t*)&C[(size_t)row * NT + col]       = *(uint32_t*)&e0;
            *(uint32_t*)&C[(size_t)(row + 8) * NT + col] = *(uint32_t*)&e1;
        }
    }
}

// ================= GEMM 2 (fp16): O = (E V) / rowsum(E) ======================
__global__ __launch_bounds__(256, 2) void gemm_pv_norm(
    const __half* __restrict__ A, const __half* __restrict__ B,
    float* __restrict__ C, size_t sA, size_t sB, size_t sC)
{
    extern __shared__ char smem[];
    __shared__ float rowinv[BM];
    const int tid = threadIdx.x;
    const int wid = tid >> 5;
    const int lane = tid & 31;
    const int g = lane >> 2;
    const int tc = lane & 3;

    A += (size_t)blockIdx.z * sA;
    B += (size_t)blockIdx.z * sB;
    C += (size_t)blockIdx.z * sC;
    const int bm = blockIdx.y * BM;
    const int bn = blockIdx.x * BN;
    const int wm = (wid & 1) * 64;
    const int wn = (wid >> 1) * 32;

    uint32_t aOff[4], bOff[2];
#pragma unroll
    for (int mt = 0; mt < 4; mt++) aOff[mt] = A_LDM_OFF(wm + mt * 16);
#pragma unroll
    for (int q = 0; q < 2; q++) bOff[q] = B_LDM_OFF(wn + q * 16) + A2_TILE_BYTES;

    float acc[4][4][4];
#pragma unroll
    for (int mt = 0; mt < 4; mt++)
#pragma unroll
        for (int nt = 0; nt < 4; nt++)
#pragma unroll
            for (int i = 0; i < 4; i++) acc[mt][nt][i] = 0.f;

    float rs[4][2];
#pragma unroll
    for (int mt = 0; mt < 4; mt++) { rs[mt][0] = 0.f; rs[mt][1] = 0.f; }

    const int nk = NT / BKH;   // 32

    ISSUE_F16(0, NT);
    ISSUE_F16(1, NT);

    for (int it = 0; it < nk; it++) {
        if (it < nk - 1) cp_wait<1>(); else cp_wait<0>();
        __syncthreads();
        if (it + 2 < nk) ISSUE_F16(it + 2, NT);

        uint32_t stg = smem_u32(smem) + (it % NSTG) * STAGE_BYTES;

#pragma unroll
        for (int ks = 0; ks < 4; ks++) {
            uint32_t koff = stg + ks * 32;
            uint32_t a[4][4], b[4][2];
#pragma unroll
            for (int mt = 0; mt < 4; mt++)
                ldmx4(a[mt][0], a[mt][1], a[mt][2], a[mt][3], koff + aOff[mt]);
            if (wid < 2) {   // wn==0 warps: exact row sums of E
#pragma unroll
                for (int mt = 0; mt < 4; mt++) {
                    float2 f0 = h2f2(a[mt][0]), f2 = h2f2(a[mt][2]);
                    float2 f1 = h2f2(a[mt][1]), f3 = h2f2(a[mt][3]);
                    rs[mt][0] += (f0.x + f0.y) + (f2.x + f2.y);
                    rs[mt][1] += (f1.x + f1.y) + (f3.x + f3.y);
                }
            }
#pragma unroll
            for (int q = 0; q < 2; q++)
                ldmx4(b[2 * q][0], b[2 * q][1], b[2 * q + 1][0], b[2 * q + 1][1],
                      koff + bOff[q]);
#pragma unroll
            for (int mt = 0; mt < 4; mt++)
#pragma unroll
                for (int nt = 0; nt < 4; nt++)
                    mma_f16(acc[mt][nt], a[mt], b[nt]);
        }
    }

    if (wid < 2) {
#pragma unroll
        for (int mt = 0; mt < 4; mt++) {
#pragma unroll
            for (int h2 = 0; h2 < 2; h2++) {
                float s = rs[mt][h2];
                s += __shfl_xor_sync(0xffffffffu, s, 1);
                s += __shfl_xor_sync(0xffffffffu, s, 2);
                if (tc == 0) rowinv[wm + mt * 16 + g + h2 * 8] = 1.f / s;
            }
        }
    }
    __syncthreads();

#pragma unroll
    for (int mt = 0; mt < 4; mt++) {
        float inv0 = rowinv[wm + mt * 16 + g];
        float inv1 = rowinv[wm + mt * 16 + g + 8];
#pragma unroll
        for (int nt = 0; nt < 4; nt++) {
            int row = bm + wm + mt * 16 + g;
            int col = bn + wn + nt * 8 + 2 * tc;
            float2 v0 = make_float2(acc[mt][nt][0] * inv0, acc[mt][nt][1] * inv0);
            float2 v1 = make_float2(acc[mt][nt][2] * inv1, acc[mt][nt][3] * inv1);
            *(float2*)&C[(size_t)row * DV + col] = v0;
            *(float2*)&C[(size_t)(row + 8) * DV + col] = v1;
        }
    }
}

// ---------------- kernel 0: x -> fp16 ----------------------------------------
__global__ __launch_bounds__(256) void conv_x(const float* __restrict__ x)
{
    size_t i = ((size_t)blockIdx.x * 256 + threadIdx.x) * 8;
    float4 v0 = *(const float4*)(x + i);
    float4 v1 = *(const float4*)(x + i + 4);
    __half2 h0 = __floats2half2_rn(v0.x, v0.y);
    __half2 h1 = __floats2half2_rn(v0.z, v0.w);
    __half2 h2 = __floats2half2_rn(v1.x, v1.y);
    __half2 h3 = __floats2half2_rn(v1.z, v1.w);
    uint4 o;
    o.x = *(uint32_t*)&h0; o.y = *(uint32_t*)&h1;
    o.z = *(uint32_t*)&h2; o.w = *(uint32_t*)&h3;
    *(uint4*)&g_xh[i] = o;
}

// ---------------- kernel 1: tensor-core QKV projection + PReLU + LN ----------
// Y[96, n] = W[96,64] * xh[64, n] per batch; LN fused in epilogue.
// Row map: 0-15 Wq(h*4+j), 16-31 Wk, 32-95 Wv(h*16+j).
// grid (NTF/256, NB), 256 threads = 8 warps as 2(M:48)x4(N:64).
#define SM_W 0                              // 96*72*2 = 13824 B
#define SM_X 13824                          // 256*72*2 = 36864 B
#define SM_OUT 50688                        // 128*97*4 = 49664 B
#define SMEM_QKV (SM_OUT + 128 * 97 * 4)    // 100352 B

__global__ __launch_bounds__(256, 1) void qkv_tc(
    const float* __restrict__ Wq, const float* __restrict__ bq, const float* __restrict__ aq,
    const float* __restrict__ gq, const float* __restrict__ betaq,
    const float* __restrict__ Wk, const float* __restrict__ bk, const float* __restrict__ ak,
    const float* __restrict__ gk, const float* __restrict__ betak,
    const float* __restrict__ Wv, const float* __restrict__ bv, const float* __restrict__ av,
    const float* __restrict__ gv, const float* __restrict__ betav)
{
    extern __shared__ char smem[];
    __half* sW = (__half*)(smem + SM_W);
    __half* sX = (__half*)(smem + SM_X);
    float* sOut = (float*)(smem + SM_OUT);

    const int tid = threadIdx.x;
    const int wid = tid >> 5;
    const int lane = tid & 31;
    const int g = lane >> 2;
    const int tc = lane & 3;
    const int b = blockIdx.y;
    const int nbase = blockIdx.x * 256;

    // --- fill W (96x64 fp16, stride QSH) ---
    for (int i = tid; i < 96 * 64; i += 256) {
        int row = i >> 6, c = i & 63;
        float w;
        if (row < 16)      w = Wq[row * NC + c];
        else if (row < 32) w = Wk[(row - 16) * NC + c];
        else               w = Wv[(row - 32) * NC + c];
        sW[row * QSH + c] = __float2half_rn(w);
    }
    // --- fill X transposed: sX[n][k], n=0..255, k=0..63 ---
    {
        const uint32_t* xp = (const uint32_t*)(g_xh + ((size_t)b * NC) * NTF + nbase);
        for (int i = tid; i < 64 * 128; i += 256) {
            int r = i >> 7;            // channel k
            int u = i & 127;           // uint within row (2 n's)
            uint32_t val = xp[(size_t)r * (NTF / 2) + u];
            __half2 hv = *(__half2*)&val;
            sX[(2 * u) * QSH + r]     = __low2half(hv);
            sX[(2 * u + 1) * QSH + r] = __high2half(hv);
        }
    }
    __syncthreads();

    // --- MMA: warp tile 48(M) x 64(N), K=64 ---
    const int wm = (wid & 1) * 48;
    const int wn = (wid >> 1) * 64;
    uint32_t sWb = smem_u32(sW);
    uint32_t sXb = smem_u32(sX);

    uint32_t a[3][4][4];
#pragma unroll
    for (int mt = 0; mt < 3; mt++) {
        uint32_t off = sWb + A_LDM_OFF_Q(wm + mt * 16);
#pragma unroll
        for (int ks = 0; ks < 4; ks++)
            ldmx4(a[mt][ks][0], a[mt][ks][1], a[mt][ks][2], a[mt][ks][3], off + ks * 32);
    }

    float acc[3][8][4];
#pragma unroll
    for (int mt = 0; mt < 3; mt++)
#pragma unroll
        for (int nt = 0; nt < 8; nt++)
#pragma unroll
            for (int i = 0; i < 4; i++) acc[mt][nt][i] = 0.f;

#pragma unroll
    for (int ks = 0; ks < 4; ks++) {
        uint32_t b2[8][2];
#pragma unroll
        for (int q = 0; q < 4; q++) {
            uint32_t off = sXb + B_LDM_OFF_Q(wn + q * 16) + ks * 32;
            ldmx4(b2[2 * q][0], b2[2 * q][1], b2[2 * q + 1][0], b2[2 * q + 1][1], off);
        }
#pragma unroll
        for (int mt = 0; mt < 3; mt++)
#pragma unroll
            for (int nt = 0; nt < 8; nt++)
                mma_f16(acc[mt][nt], a[mt][ks], b2[nt]);
    }

    // --- epilogue in two 128-column batches ---
#pragma unroll 1
    for (int bt = 0; bt < 2; bt++) {
        __syncthreads();
        if ((wid >> 2) == bt) {   // warps covering cols [bt*128, bt*128+128)
#pragma unroll
            for (int mt = 0; mt < 3; mt++)
#pragma unroll
                for (int nt = 0; nt < 8; nt++)
#pragma unroll
                    for (int i = 0; i < 4; i++) {
                        int row = wm + mt * 16 + g + 8 * (i >> 1);
                        int col = (wn - bt * 128) + nt * 8 + 2 * tc + (i & 1);
                        sOut[col * 97 + row] = acc[mt][nt][i];
                    }
        }
        __syncthreads();
        if (tid < 128) {
            const int c = tid;
            const int n = nbase + bt * 128 + c;
            const int t = n >> 6;
            const int f = n & 63;
            const float* so = sOut + c * 97;

#pragma unroll
            for (int h = 0; h < NH; h++) {
                // Q (rows 4h..4h+3)
                {
                    float y[4]; float aph = aq[h]; float mu = 0.f;
#pragma unroll
                    for (int j = 0; j < 4; j++) {
                        float v = so[4 * h + j] + bq[4 * h + j];
                        v = (v >= 0.f) ? v : aph * v;
                        y[j] = v; mu += v;
                    }
                    mu *= 0.25f;
                    float var = 0.f;
#pragma unroll
                    for (int j = 0; j < 4; j++) { float d = y[j] - mu; var += d * d; }
                    float r = rsqrtf(var * 0.25f + EPSV);
#pragma unroll
                    for (int j = 0; j < 4; j++) {
                        float o = (y[j] - mu) * r * gq[4 * h + j] + betaq[4 * h + j];
                        g_Q[((size_t)(h * NB + b) * NT + t) * DQK + j * NF + f] = __float2half_rn(o);
                    }
                }
                // K (rows 16+4h..)
                {
                    float y[4]; float aph = ak[h]; float mu = 0.f;
#pragma unroll
                    for (int j = 0; j < 4; j++) {
                        float v = so[16 + 4 * h + j] + bk[4 * h + j];
                        v = (v >= 0.f) ? v : aph * v;
                        y[j] = v; mu += v;
                    }
                    mu *= 0.25f;
                    float var = 0.f;
#pragma unroll
                    for (int j = 0; j < 4; j++) { float d = y[j] - mu; var += d * d; }
                    float r = rsqrtf(var * 0.25f + EPSV);
#pragma unroll
                    for (int j = 0; j < 4; j++) {
                        float o = (y[j] - mu) * r * gk[4 * h + j] + betak[4 * h + j];
                        g_K[((size_t)(h * NB + b) * NT + t) * DQK + j * NF + f] = __float2half_rn(o);
                    }
                }
                // V (rows 32+16h..)
                {
                    float y[16]; float aph = av[h]; float mu = 0.f;
#pragma unroll
                    for (int j = 0; j < 16; j++) {
                        float v = so[32 + 16 * h + j] + bv[16 * h + j];
                        v = (v >= 0.f) ? v : aph * v;
                        y[j] = v; mu += v;
                    }
                    mu *= (1.f / 16.f);
                    float var = 0.f;
#pragma unroll
                    for (int j = 0; j < 16; j++) { float d = y[j] - mu; var += d * d; }
                    float r = rsqrtf(var * (1.f / 16.f) + EPSV);
#pragma unroll
                    for (int j = 0; j < 16; j++) {
                        float o = (y[j] - mu) * r * gv[16 * h + j] + betav[16 * h + j];
                        g_V[((size_t)(h * NB + b) * NT + t) * DV + j * NF + f] = __float2half_rn(o);
                    }
                }
            }
        }
    }
}

// ---------------- transpose V (fp16): [t][dv] -> [dv][t] per z ----------------
__global__ __launch_bounds__(256) void transpose_v()
{
    __shared__ __half tile[32][33];
    int bt = blockIdx.x * 32, bd = blockIdx.y * 32;
    size_t base = (size_t)blockIdx.z * NT * DV;
    int tx = threadIdx.x, ty = threadIdx.y;
#pragma unroll
    for (int j = 0; j < 4; j++)
        tile[ty + j * 8][tx] = g_V[base + (size_t)(bt + ty + j * 8) * DV + bd + tx];
    __syncthreads();
#pragma unroll
    for (int j = 0; j < 4; j++)
        g_Vt[base + (size_t)(bd + ty + j * 8) * NT + bt + tx] = tile[tx][ty + j * 8];
}

// ---------------- output projection + PReLU + LN + residual ------------------
__global__ __launch_bounds__(256) void out_kernel(
    const float* __restrict__ x,
    const float* __restrict__ Wp, const float* __restrict__ bp, const float* __restrict__ ap,
    const float* __restrict__ gp, const float* __restrict__ betap,
    float* __restrict__ out)
{
    __shared__ float sWt[NC * 68];     // [c][o]
    __shared__ float sOg[NC * 68];     // [c][f]
    __shared__ float sred1[4][64];
    __shared__ float sred2[4][64];

    const int tid = threadIdx.x;
    const int t = blockIdx.x;
    const int b = blockIdx.y;

    for (int i = tid; i < NC * NC; i += 256) {
        int o = i >> 6, c = i & 63;
        sWt[c * 68 + o] = Wp[i];
    }
#pragma unroll
    for (int h = 0; h < NH; h++) {
        const float4* src = (const float4*)&g_O[((size_t)(h * NB + b) * NT + t) * DV];
        float4 val = src[tid];
        int vc = tid >> 4;
        int f0 = (tid & 15) * 4;
        *(float4*)&sOg[(h * 16 + vc) * 68 + f0] = val;
    }
    __syncthreads();

    const int j = tid >> 6;
    const int f = tid & 63;
    const int o0 = 16 * j;

    float acc[16];
#pragma unroll
    for (int i = 0; i < 16; i++) acc[i] = 0.f;

#pragma unroll 8
    for (int c = 0; c < NC; c++) {
        float og = sOg[c * 68 + f];
        float4 w0 = *(const float4*)&sWt[c * 68 + o0];
        float4 w1 = *(const float4*)&sWt[c * 68 + o0 + 4];
        float4 w2 = *(const float4*)&sWt[c * 68 + o0 + 8];
        float4 w3 = *(const float4*)&sWt[c * 68 + o0 + 12];
        acc[0] += w0.x * og;  acc[1] += w0.y * og;  acc[2] += w0.z * og;  acc[3] += w0.w * og;
        acc[4] += w1.x * og;  acc[5] += w1.y * og;  acc[6] += w1.z * og;  acc[7] += w1.w * og;
        acc[8] += w2.x * og;  acc[9] += w2.y * og;  acc[10] += w2.z * og; acc[11] += w2.w * og;
        acc[12] += w3.x * og; acc[13] += w3.y * og; acc[14] += w3.z * og; acc[15] += w3.w * og;
    }

    float a = ap[0];
    float s1 = 0.f, s2 = 0.f;
#pragma unroll
    for (int i = 0; i < 16; i++) {
        float y = acc[i] + bp[o0 + i];
        y = (y >= 0.f) ? y : a * y;
        acc[i] = y;
        s1 += y; s2 += y * y;
    }
    sred1[j][f] = s1;
    sred2[j][f] = s2;
    __syncthreads();
    s1 = sred1[0][f] + sred1[1][f] + sred1[2][f] + sred1[3][f];
    s2 = sred2[0][f] + sred2[1][f] + sred2[2][f] + sred2[3][f];
    float mu = s1 * (1.f / NC);
    float var = s2 * (1.f / NC) - mu * mu;
    float r = rsqrtf(var + EPSV);

#pragma unroll
    for (int i = 0; i < 16; i++) {
        int o = o0 + i;
        size_t idx = (((size_t)b * NC + o) * NT + t) * NF + f;
        out[idx] = (acc[i] - mu) * r * gp[o] + betap[o] + x[idx];
    }
}

// ---------------- launch ------------------------------------------------------
extern "C" void kernel_launch(void* const* d_in, const int* in_sizes, int n_in,
                              void* d_out, int out_size)
{
    const float* x     = (const float*)d_in[0];
    const float* Wq    = (const float*)d_in[1];
    const float* bq    = (const float*)d_in[2];
    const float* aq    = (const float*)d_in[3];
    const float* gq    = (const float*)d_in[4];
    const float* betaq = (const float*)d_in[5];
    const float* Wk    = (const float*)d_in[6];
    const float* bk    = (const float*)d_in[7];
    const float* ak    = (const float*)d_in[8];
    const float* gk    = (const float*)d_in[9];
    const float* betak = (const float*)d_in[10];
    const float* Wv    = (const float*)d_in[11];
    const float* bv    = (const float*)d_in[12];
    const float* av    = (const float*)d_in[13];
    const float* gv    = (const float*)d_in[14];
    const float* betav = (const float*)d_in[15];
    const float* Wp    = (const float*)d_in[16];
    const float* bp    = (const float*)d_in[17];
    const float* ap    = (const float*)d_in[18];
    const float* gp    = (const float*)d_in[19];
    const float* betap = (const float*)d_in[20];
    float* out = (float*)d_out;

    float* pO;
    __half *pQ, *pK, *pV, *pVt, *pE;
    cudaGetSymbolAddress((void**)&pQ, g_Q);
    cudaGetSymbolAddress((void**)&pK, g_K);
    cudaGetSymbolAddress((void**)&pV, g_V);
    cudaGetSymbolAddress((void**)&pVt, g_Vt);
    cudaGetSymbolAddress((void**)&pE, g_E);
    cudaGetSymbolAddress((void**)&pO, g_O);

    cudaFuncSetAttribute(gemm_qk_exp, cudaFuncAttributeMaxDynamicSharedMemorySize, SMEM_GEMM);
    cudaFuncSetAttribute(gemm_pv_norm, cudaFuncAttributeMaxDynamicSharedMemorySize, SMEM_GEMM);
    cudaFuncSetAttribute(qkv_tc, cudaFuncAttributeMaxDynamicSharedMemorySize, SMEM_QKV);

    // 0) x -> fp16
    conv_x<<<(NB * NC * (size_t)NTF) / (256 * 8), 256>>>(x);

    // 1) QKV projection (tensor cores) + PReLU + LN
    qkv_tc<<<dim3(NTF / 256, NB), 256, SMEM_QKV>>>(
        Wq, bq, aq, gq, betaq, Wk, bk, ak, gk, betak, Wv, bv, av, gv, betav);

    // 2) V transpose (fp16): [t][dv] -> [dv][t]
    transpose_v<<<dim3(NT / 32, DV / 32, NHB), dim3(32, 8)>>>();

    // 3) E = fp16(exp((1/16) Q K^T))
    gemm_qk_exp<<<dim3(NT / BN, NT / BM, NHB), 256, SMEM_GEMM>>>(
        pQ, pK, pE, 0.0625f,
        (size_t)NT * DQK, (size_t)NT * DQK, (size_t)NT * NT);

    // 4) O = (E V) / rowsum(E)
    gemm_pv_norm<<<dim3(DV / BN, NT / BM, NHB), 256, SMEM_GEMM>>>(
        pE, pVt, pO,
        (size_t)NT * NT, (size_t)DV * NT, (size_t)NT * DV);

    // 5) output projection + LN + residual
    out_kernel<<<dim3(NT, NB), 256>>>(
        x, Wp, bp, ap, gp, betap, out);
}